// round 1
// baseline (speedup 1.0000x reference)
#include <cuda_runtime.h>
#include <math.h>

#define BB 2
#define TT 512
#define DD 64
#define LAYERS 4
#define HH 32
#define NTOK (BB*TT)
#define FDIM 192
#define EPSF 1e-8f
// sqrt(EPS/2), EPS/(2*sqrt(2))
#define C2F 7.0710678e-5f
#define C3F 3.5355339e-9f

__device__ float g_bufA[NTOK*DD];
__device__ float g_bufB[NTOK*DD];
__device__ float g_prev[LAYERS][NTOK*DD];
__device__ float g_feat[NTOK*FDIM];
__device__ float g_basin[DD];
__device__ float g_temps[LAYERS];

// ---------------------------------------------------------------------------
// init: basin = basin_coords; temps for pass 0
__global__ void k_init(const float* __restrict__ basin_coords,
                       const float* __restrict__ W_temp,
                       const float* __restrict__ b_temp) {
    int t = threadIdx.x;           // 64 threads
    __shared__ float sb[DD];
    sb[t] = basin_coords[t];
    g_basin[t] = sb[t];
    __syncthreads();
    if (t < LAYERS) {
        float acc = b_temp[t];
        #pragma unroll 8
        for (int d = 0; d < DD; ++d) acc = fmaf(W_temp[t*DD + d], sb[d], acc);
        g_temps[t] = 1.f/(1.f + expf(-acc)) + 0.5f;
    }
}

// ---------------------------------------------------------------------------
// feat: optional feedback gate (in-place x update), then simplex projection +
// factored Bhattacharyya features (u, v, t). One block per token, 64 threads.
__global__ void k_feat(int cursel, int l, int gated,
                       const float* __restrict__ W_fb,
                       const float* __restrict__ b_fb) {
    float* x = cursel ? g_bufB : g_bufA;
    int tok = blockIdx.x, d = threadIdx.x;
    __shared__ float sx[DD], spv[DD];
    __shared__ float red1[2], red2[2];

    float xv = x[tok*DD + d];
    if (gated) {
        sx[d]  = xv;
        spv[d] = g_prev[l][tok*DD + d];
        __syncthreads();
        const float* Wr = W_fb + (l*DD + d)*2*DD;
        float acc = b_fb[l*DD + d];
        #pragma unroll 8
        for (int k = 0; k < DD; ++k) acc = fmaf(sx[k],  Wr[k],      acc);
        #pragma unroll 8
        for (int k = 0; k < DD; ++k) acc = fmaf(spv[k], Wr[DD + k], acc);
        float g = 1.f/(1.f + expf(-acc));
        xv = xv*g + spv[d]*(1.f - g);
        x[tok*DD + d] = xv;
    }

    // softplus (stable, matches jax logaddexp(x,0))
    float sp = fmaxf(xv, 0.f) + log1pf(expf(-fabsf(xv)));

    // first normalization
    float v = sp;
    #pragma unroll
    for (int o = 16; o; o >>= 1) v += __shfl_xor_sync(0xffffffffu, v, o);
    if ((d & 31) == 0) red1[d >> 5] = v;
    __syncthreads();
    float s1 = red1[0] + red1[1];
    float s = fmaxf(sp/(s1 + EPSF), EPSF);

    // second normalization (fisher_rao renormalizes again)
    v = s;
    #pragma unroll
    for (int o = 16; o; o >>= 1) v += __shfl_xor_sync(0xffffffffu, v, o);
    if ((d & 31) == 0) red2[d >> 5] = v;
    __syncthreads();
    float s2 = red2[0] + red2[1];
    float p = s/(s2 + EPSF);

    float u  = sqrtf(p);
    float vf = C2F/u;          // v_i v_j = eps/(2 sqrt(p_i p_j))
    float tf = C3F/(p*u);      // t_i t_j = eps^2/(8 (p_i p_j)^{3/2})

    float* f = g_feat + tok*FDIM;
    f[d]        = u;
    f[DD + d]   = vf;
    f[128 + d]  = tf;
}

// ---------------------------------------------------------------------------
// attention: 8 rows per block, 256 threads (8 warps), warps split j-range.
// inner_ij = sum(u,v) - sum(t) done as a 192-dot with the t-segment negated
// on the row side. Two-pass softmax via smem logits tile; value accumulation
// with lanes = dims; cross-warp merge at the end.
__global__ void __launch_bounds__(256)
k_attn(int cursel, int l, int snap) {
    const float* xin = cursel ? g_bufB : g_bufA;
    float*       xout = cursel ? g_bufA : g_bufB;
    float* prevOut = snap ? &g_prev[l][0] : nullptr;

    int blk = blockIdx.x;
    int b = blk / (TT/8);
    int rowBase = (blk % (TT/8)) * 8;
    int tid = threadIdx.x, w = tid >> 5, c = tid & 31;

    __shared__ __align__(16) float rf[8][FDIM];   // row features (t negated)
    __shared__ float Lg[8][TT];                   // logits, then exp weights
    __shared__ float wMax[8][8], Mrow[8], wSsum[8][8];
    __shared__ float wFacc[8][8][DD];

    float temp = fmaxf(g_temps[l], 1e-6f);
    float nInvT = -1.f/temp;
    float res = 0.f;  // res filled below via global read of res_scale passed in const mem? -> passed via g? use param-free: res read later
    // res_scale is small; fetch from constant-like global param array:
    // (passed through kernel arg instead)
    res = 0.f; // placeholder, real value set by k_attn2 wrapper — see below
    (void)res;

    // load row features, negate t-segment
    for (int idx = tid; idx < 8*FDIM; idx += 256) {
        int r = idx / FDIM, dd = idx - r*FDIM;
        float fv = g_feat[(b*TT + rowBase + r)*FDIM + dd];
        rf[r][dd] = (dd < 128) ? fv : -fv;
    }
    __syncthreads();

    // phase 1: logits for this warp's 64 j's
    float mymax[8];
    #pragma unroll
    for (int r = 0; r < 8; ++r) mymax[r] = -INFINITY;

    #pragma unroll
    for (int chunk = 0; chunk < 2; ++chunk) {
        int jl = w*64 + chunk*32 + c;
        const float* jf = g_feat + (b*TT + jl)*FDIM;
        float acc[8];
        #pragma unroll
        for (int r = 0; r < 8; ++r) acc[r] = 0.f;
        #pragma unroll 4
        for (int dd = 0; dd < FDIM; dd += 4) {
            float4 jv = *(const float4*)(jf + dd);
            #pragma unroll
            for (int r = 0; r < 8; ++r) {
                float4 rv = *(const float4*)(&rf[r][dd]);
                acc[r] += rv.x*jv.x + rv.y*jv.y + rv.z*jv.z + rv.w*jv.w;
            }
        }
        #pragma unroll
        for (int r = 0; r < 8; ++r) {
            float inner = fminf(fmaxf(acc[r], -1.f + 1e-6f), 1.f - 1e-6f);
            float lgv = 2.f*acosf(inner)*nInvT;
            Lg[r][jl] = lgv;
            mymax[r] = fmaxf(mymax[r], lgv);
        }
    }
    #pragma unroll
    for (int r = 0; r < 8; ++r) {
        float m = mymax[r];
        #pragma unroll
        for (int o = 16; o; o >>= 1) m = fmaxf(m, __shfl_xor_sync(0xffffffffu, m, o));
        if (c == 0) wMax[w][r] = m;
    }
    __syncthreads();
    if (tid < 8) {
        float m = wMax[0][tid];
        #pragma unroll
        for (int ww = 1; ww < 8; ++ww) m = fmaxf(m, wMax[ww][tid]);
        Mrow[tid] = m;
    }
    __syncthreads();

    // phase 3: exp + per-warp partial row-sums; overwrite Lg with e
    float ps[8];
    #pragma unroll
    for (int r = 0; r < 8; ++r) ps[r] = 0.f;
    #pragma unroll
    for (int chunk = 0; chunk < 2; ++chunk) {
        int jl = w*64 + chunk*32 + c;
        #pragma unroll
        for (int r = 0; r < 8; ++r) {
            float e = expf(Lg[r][jl] - Mrow[r]);
            Lg[r][jl] = e;
            ps[r] += e;
        }
    }
    #pragma unroll
    for (int r = 0; r < 8; ++r) {
        float sv = ps[r];
        #pragma unroll
        for (int o = 16; o; o >>= 1) sv += __shfl_xor_sync(0xffffffffu, sv, o);
        if (c == 0) wSsum[w][r] = sv;
    }
    __syncwarp();

    // phase 4: weighted value accumulation (lanes = dims c, c+32)
    float f0[8], f1[8];
    #pragma unroll
    for (int r = 0; r < 8; ++r) { f0[r] = 0.f; f1[r] = 0.f; }
    const float* xb = xin + b*TT*DD;
    for (int jj = 0; jj < 64; ++jj) {
        int jl = w*64 + jj;
        float xv0 = xb[jl*DD + c];
        float xv1 = xb[jl*DD + c + 32];
        #pragma unroll
        for (int r = 0; r < 8; ++r) {
            float e = Lg[r][jl];
            f0[r] = fmaf(e, xv0, f0[r]);
            f1[r] = fmaf(e, xv1, f1[r]);
        }
    }
    #pragma unroll
    for (int r = 0; r < 8; ++r) {
        wFacc[w][r][c]      = f0[r];
        wFacc[w][r][c + 32] = f1[r];
    }
    __syncthreads();

    // phase 5: merge across warps; warp w owns row r = w
    {
        int r = w;
        float F0 = 0.f, F1 = 0.f, S = 0.f;
        #pragma unroll
        for (int ww = 0; ww < 8; ++ww) {
            F0 += wFacc[ww][r][c];
            F1 += wFacc[ww][r][c + 32];
            S  += wSsum[ww][r];
        }
        int tok = b*TT + rowBase + r;
        float resv = g_feat[0]*0.f;  // dummy to keep structure; real res below
        (void)resv;
        float rsc;
        rsc = __ldg(&g_temps[0])*0.f; (void)rsc;
        // res_scale passed via device global set below
        extern __device__ float g_res_scale_copy[LAYERS];
        float rs = g_res_scale_copy[l];
        float xv0 = xin[tok*DD + c], xv1 = xin[tok*DD + c + 32];
        float o0 = xv0 + rs*(F0/S - xv0);
        float o1 = xv1 + rs*(F1/S - xv1);
        xout[tok*DD + c]      = o0;
        xout[tok*DD + c + 32] = o1;
        if (prevOut) {
            prevOut[tok*DD + c]      = o0;
            prevOut[tok*DD + c + 32] = o1;
        }
    }
}

__device__ float g_res_scale_copy[LAYERS];

__global__ void k_copy_res(const float* __restrict__ res_scale) {
    if (threadIdx.x < LAYERS) g_res_scale_copy[threadIdx.x] = res_scale[threadIdx.x];
}

// ---------------------------------------------------------------------------
// pool + compress MLP + basin update + temps for next pass. One block, 128 thr.
__global__ void k_pool(int cursel,
                       const float* __restrict__ Wc1, const float* __restrict__ bc1,
                       const float* __restrict__ Wc2, const float* __restrict__ bc2,
                       const float* __restrict__ Wu,  const float* __restrict__ bu,
                       const float* __restrict__ W_temp, const float* __restrict__ b_temp) {
    const float* x = cursel ? g_bufB : g_bufA;
    int tid = threadIdx.x;
    __shared__ float pooled[BB][DD];
    __shared__ float h1[BB][HH];
    __shared__ float hb[BB][DD];
    __shared__ float agg[DD], comb[2*DD], nb[DD];

    int b = tid / DD, d = tid - b*DD;
    {
        float s = 0.f;
        const float* xb = x + b*TT*DD + d;
        #pragma unroll 8
        for (int t = 0; t < TT; ++t) s += xb[t*DD];
        pooled[b][d] = s * (1.f/TT);
    }
    __syncthreads();
    if (tid < BB*HH) {
        int bb = tid / HH, h = tid - bb*HH;
        float a = bc1[h];
        #pragma unroll 8
        for (int k = 0; k < DD; ++k) a = fmaf(pooled[bb][k], Wc1[h*DD + k], a);
        h1[bb][h] = tanhf(a);
    }
    __syncthreads();
    {
        float a = bc2[d];
        #pragma unroll 8
        for (int k = 0; k < HH; ++k) a = fmaf(h1[b][k], Wc2[d*HH + k], a);
        hb[b][d] = tanhf(a);
    }
    __syncthreads();
    if (tid < DD) {
        float a = 0.5f*(hb[0][tid] + hb[1][tid]);
        agg[tid]      = a;
        comb[tid]     = g_basin[tid];
        comb[DD+tid]  = a;
    }
    __syncthreads();
    if (tid < DD) {
        float a = bu[tid];
        #pragma unroll 8
        for (int k = 0; k < 2*DD; ++k) a = fmaf(Wu[tid*2*DD + k], comb[k], a);
        float g = 1.f/(1.f + expf(-a));
        nb[tid] = g_basin[tid]*(1.f - g) + agg[tid]*g;
        g_basin[tid] = nb[tid];
    }
    __syncthreads();
    if (tid < LAYERS) {
        float acc = b_temp[tid];
        #pragma unroll 8
        for (int k = 0; k < DD; ++k) acc = fmaf(W_temp[tid*DD + k], nb[k], acc);
        g_temps[tid] = 1.f/(1.f + expf(-acc)) + 0.5f;
    }
}

// ---------------------------------------------------------------------------
__global__ void k_final(int cursel, const float* __restrict__ seq,
                        const float* __restrict__ res_g, float* __restrict__ out) {
    const float* x = cursel ? g_bufB : g_bufA;
    int i = blockIdx.x*blockDim.x + threadIdx.x;
    if (i < NTOK*DD) {
        float xv = x[i];
        out[i] = xv + 0.01f * res_g[0] * (xv - seq[i]);
    }
}

// ---------------------------------------------------------------------------
extern "C" void kernel_launch(void* const* d_in, const int* in_sizes, int n_in,
                              void* d_out, int out_size) {
    const float* basin_seq    = (const float*)d_in[0];
    const float* basin_coords = (const float*)d_in[1];
    const float* W_temp       = (const float*)d_in[2];
    const float* b_temp       = (const float*)d_in[3];
    const float* res_scale    = (const float*)d_in[4];
    const float* W_fb         = (const float*)d_in[5];
    const float* b_fb         = (const float*)d_in[6];
    const float* Wc1          = (const float*)d_in[7];
    const float* bc1          = (const float*)d_in[8];
    const float* Wc2          = (const float*)d_in[9];
    const float* bc2          = (const float*)d_in[10];
    const float* Wu           = (const float*)d_in[11];
    const float* bu           = (const float*)d_in[12];
    const float* res_g        = (const float*)d_in[13];

    // x <- basin_seq into buffer A
    cudaMemcpyToSymbolAsync(g_bufA, basin_seq, NTOK*DD*sizeof(float), 0,
                            cudaMemcpyDeviceToDevice, 0);
    k_copy_res<<<1, 32>>>(res_scale);
    k_init<<<1, 64>>>(basin_coords, W_temp, b_temp);

    int cursel = 0;
    for (int p = 0; p < 2; ++p) {
        for (int l = 0; l < LAYERS; ++l) {
            k_feat<<<NTOK, 64>>>(cursel, l, p > 0 ? 1 : 0, W_fb, b_fb);
            k_attn<<<NTOK/8, 256>>>(cursel, l, p == 0 ? 1 : 0);
            cursel ^= 1;
        }
        if (p == 0) {
            k_pool<<<1, 128>>>(cursel, Wc1, bc1, Wc2, bc2, Wu, bu, W_temp, b_temp);
        }
    }
    k_final<<<(NTOK*DD + 255)/256, 256>>>(cursel, basin_seq, res_g, (float*)d_out);
}

// round 2
// speedup vs baseline: 1.0056x; 1.0056x over previous
#include <cuda_runtime.h>
#include <math.h>

#define BB 2
#define TT 512
#define DD 64
#define LAYERS 4
#define HH 32
#define NTOK (BB*TT)
#define FDIM 192
#define EPSF 1e-8f
// sqrt(EPS/2), EPS/(2*sqrt(2))
#define C2F 7.0710678e-5f
#define C3F 3.5355339e-9f

__device__ float g_bufA[NTOK*DD];
__device__ float g_bufB[NTOK*DD];
__device__ float g_prev[LAYERS][NTOK*DD];
__device__ float g_featT[FDIM*NTOK];     // [dim][token] -- coalesced j-loads
__device__ float g_basin[DD];
__device__ float g_temps[LAYERS];
__device__ float g_res[LAYERS];

// acos for x in [-1,1], |err| ~2e-8 (A&S 4.4.45, 8 coeffs)
__device__ __forceinline__ float acos_fast(float x) {
    float ax = fabsf(x);
    float r = sqrtf(1.0f - ax);
    float p = fmaf(ax, -0.0012624911f, 0.0066700901f);
    p = fmaf(ax, p, -0.0170881256f);
    p = fmaf(ax, p, 0.0308918810f);
    p = fmaf(ax, p, -0.0501743046f);
    p = fmaf(ax, p, 0.0889789874f);
    p = fmaf(ax, p, -0.2145988016f);
    p = fmaf(ax, p, 1.5707963050f);
    float res = r * p;
    return (x < 0.f) ? (3.14159265358979f - res) : res;
}

// ---------------------------------------------------------------------------
__global__ void k_init(const float* __restrict__ basin_coords,
                       const float* __restrict__ W_temp,
                       const float* __restrict__ b_temp,
                       const float* __restrict__ res_scale) {
    int t = threadIdx.x;           // 64 threads
    __shared__ float sb[DD];
    sb[t] = basin_coords[t];
    g_basin[t] = sb[t];
    __syncthreads();
    if (t < LAYERS) {
        g_res[t] = res_scale[t];
        float acc = b_temp[t];
        #pragma unroll 8
        for (int d = 0; d < DD; ++d) acc = fmaf(W_temp[t*DD + d], sb[d], acc);
        g_temps[t] = 1.f/(1.f + expf(-acc)) + 0.5f;
    }
}

// ---------------------------------------------------------------------------
// feat: 8 tokens per block, 128 threads. Optional feedback gate with weights
// staged in smem (stride 133 => conflict-free), then simplex projection +
// factored Bhattacharyya features written transposed: featT[dim][token].
__global__ void __launch_bounds__(128) k_feat(int cursel, int l, int gated,
        const float* __restrict__ W_fb, const float* __restrict__ b_fb) {
    float* x = cursel ? g_bufB : g_bufA;
    int tid = threadIdx.x;
    int tok0 = blockIdx.x * 8;
    __shared__ float sW[64*133];
    __shared__ float sx[8][64], spv[8][64], sxn[8][64], st[8][64];
    __shared__ float ssum[8];

    for (int i = tid; i < 8*64; i += 128) sx[i>>6][i&63] = x[tok0*64 + i];

    if (gated) {
        for (int i = tid; i < 8*64; i += 128)
            spv[i>>6][i&63] = g_prev[l][tok0*64 + i];
        for (int i = tid; i < 64*128; i += 128)
            sW[(i>>7)*133 + (i&127)] = W_fb[l*64*128 + i];
        __syncthreads();
        #pragma unroll
        for (int rep = 0; rep < 4; ++rep) {
            int tok = rep*2 + (tid>>6);
            int d = tid & 63;
            const float* Wr = &sW[d*133];
            float acc = b_fb[l*64 + d];
            #pragma unroll 8
            for (int k = 0; k < 64; ++k) acc = fmaf(sx[tok][k], Wr[k], acc);
            #pragma unroll 8
            for (int k = 0; k < 64; ++k) acc = fmaf(spv[tok][k], Wr[64+k], acc);
            float g = 1.f/(1.f + __expf(-acc));
            float xv = sx[tok][d]*g + spv[tok][d]*(1.f-g);
            sxn[tok][d] = xv;
            x[(tok0+tok)*64 + d] = xv;
        }
    } else {
        __syncthreads();
        for (int i = tid; i < 8*64; i += 128) sxn[i>>6][i&63] = sx[i>>6][i&63];
    }
    __syncthreads();

    // stable softplus
    for (int i = tid; i < 8*64; i += 128) {
        float xv = sxn[i>>6][i&63];
        st[i>>6][i&63] = fmaxf(xv, 0.f) + log1pf(expf(-fabsf(xv)));
    }
    __syncthreads();
    if (tid < 8) { float s = 0.f; for (int k = 0; k < 64; ++k) s += st[tid][k]; ssum[tid] = s + EPSF; }
    __syncthreads();
    for (int i = tid; i < 8*64; i += 128) {
        int t8 = i>>6;
        st[t8][i&63] = fmaxf(st[t8][i&63]/ssum[t8], EPSF);
    }
    __syncthreads();
    if (tid < 8) { float s = 0.f; for (int k = 0; k < 64; ++k) s += st[tid][k]; ssum[tid] = s + EPSF; }
    __syncthreads();
    for (int i = tid; i < 8*64; i += 128) {
        int t8 = i>>6, d = i&63;
        float p = st[t8][d]/ssum[t8];
        int gt = tok0 + t8;
        float u = sqrtf(p);
        g_featT[d*NTOK + gt]        = u;
        g_featT[(64+d)*NTOK + gt]   = C2F/u;      // v_i v_j = eps/(2 sqrt(pi pj))
        g_featT[(128+d)*NTOK + gt]  = C3F/(p*u);  // t_i t_j = eps^2/(8 (pi pj)^1.5)
    }
}

// ---------------------------------------------------------------------------
// attention: 4 rows per block, grid = B*T/4 = 256, 256 threads (8 warps).
// Warp w owns j in [w*64, w*64+64), each lane 2 j's via coalesced float2
// loads from transposed features. Two-pass softmax with smem logits tile.
__global__ void __launch_bounds__(256)
k_attn(int cursel, int l, int snap) {
    const float* xin = cursel ? g_bufB : g_bufA;
    float*       xout = cursel ? g_bufA : g_bufB;

    int blk = blockIdx.x;
    int b = blk >> 7;                    // / 128
    int rowBase = (blk & 127) << 2;      // *4
    int tid = threadIdx.x, w = tid >> 5, c = tid & 31;

    __shared__ float rf[4][FDIM];        // row features, t-segment negated
    __shared__ float Lg[4][TT];          // logits -> exp weights
    __shared__ float wMax[8][4], Mrow[4], wSum[8][4];
    __shared__ float wFacc[8][4][DD];

    float nInvT = -1.f / fmaxf(g_temps[l], 1e-6f);

    for (int idx = tid; idx < 4*FDIM; idx += 256) {
        int r = idx / FDIM, dd = idx - r*FDIM;
        float fv = g_featT[dd*NTOK + b*TT + rowBase + r];
        rf[r][dd] = (dd < 128) ? fv : -fv;
    }
    __syncthreads();

    // phase 1: inner products (192-dot) for this warp's 64 j's (2 per lane)
    int jbase = b*TT + w*64;
    float acc[4][2];
    #pragma unroll
    for (int r = 0; r < 4; ++r) { acc[r][0] = 0.f; acc[r][1] = 0.f; }
    #pragma unroll 4
    for (int dd = 0; dd < FDIM; ++dd) {
        float2 jv = ((const float2*)(g_featT + dd*NTOK + jbase))[c];
        #pragma unroll
        for (int r = 0; r < 4; ++r) {
            float rv = rf[r][dd];
            acc[r][0] = fmaf(rv, jv.x, acc[r][0]);
            acc[r][1] = fmaf(rv, jv.y, acc[r][1]);
        }
    }
    float lmax[4];
    #pragma unroll
    for (int r = 0; r < 4; ++r) {
        float i0 = fminf(fmaxf(acc[r][0], -1.f + 1e-6f), 1.f - 1e-6f);
        float i1 = fminf(fmaxf(acc[r][1], -1.f + 1e-6f), 1.f - 1e-6f);
        float lg0 = 2.f*acos_fast(i0)*nInvT;
        float lg1 = 2.f*acos_fast(i1)*nInvT;
        ((float2*)&Lg[r][w*64])[c] = make_float2(lg0, lg1);
        lmax[r] = fmaxf(lg0, lg1);
    }
    #pragma unroll
    for (int r = 0; r < 4; ++r) {
        float m = lmax[r];
        #pragma unroll
        for (int o = 16; o; o >>= 1) m = fmaxf(m, __shfl_xor_sync(0xffffffffu, m, o));
        if (c == 0) wMax[w][r] = m;
    }
    __syncthreads();
    if (tid < 4) {
        float m = wMax[0][tid];
        #pragma unroll
        for (int ww = 1; ww < 8; ++ww) m = fmaxf(m, wMax[ww][tid]);
        Mrow[tid] = m;
    }
    __syncthreads();

    // phase 2: exp + per-warp partial sums (own j-range only; no block sync needed)
    float ps[4];
    #pragma unroll
    for (int r = 0; r < 4; ++r) {
        float2* Lp = (float2*)&Lg[r][w*64];
        float2 v = Lp[c];
        float e0 = __expf(v.x - Mrow[r]);
        float e1 = __expf(v.y - Mrow[r]);
        Lp[c] = make_float2(e0, e1);
        ps[r] = e0 + e1;
    }
    #pragma unroll
    for (int r = 0; r < 4; ++r) {
        float sv = ps[r];
        #pragma unroll
        for (int o = 16; o; o >>= 1) sv += __shfl_xor_sync(0xffffffffu, sv, o);
        if (c == 0) wSum[w][r] = sv;
    }
    __syncwarp();

    // phase 3: weighted value accumulation (lanes = dims c, c+32), own j-range
    float f0[4] = {0.f,0.f,0.f,0.f}, f1[4] = {0.f,0.f,0.f,0.f};
    const float* xb = xin + b*TT*DD;
    #pragma unroll 2
    for (int jj = 0; jj < 64; ++jj) {
        int jl = w*64 + jj;
        float xv0 = xb[jl*DD + c];
        float xv1 = xb[jl*DD + c + 32];
        #pragma unroll
        for (int r = 0; r < 4; ++r) {
            float e = Lg[r][jl];
            f0[r] = fmaf(e, xv0, f0[r]);
            f1[r] = fmaf(e, xv1, f1[r]);
        }
    }
    #pragma unroll
    for (int r = 0; r < 4; ++r) {
        wFacc[w][r][c]      = f0[r];
        wFacc[w][r][c + 32] = f1[r];
    }
    __syncthreads();

    // phase 4: merge across warps; warps 0..3 own one row each
    if (w < 4) {
        int r = w;
        float F0 = 0.f, F1 = 0.f, S = 0.f;
        #pragma unroll
        for (int ww = 0; ww < 8; ++ww) {
            F0 += wFacc[ww][r][c];
            F1 += wFacc[ww][r][c + 32];
            S  += wSum[ww][r];
        }
        int tok = b*TT + rowBase + r;
        float rs = g_res[l];
        float inv = 1.f/S;
        float xv0 = xin[tok*DD + c], xv1 = xin[tok*DD + c + 32];
        float o0 = xv0 + rs*(F0*inv - xv0);
        float o1 = xv1 + rs*(F1*inv - xv1);
        xout[tok*DD + c]      = o0;
        xout[tok*DD + c + 32] = o1;
        if (snap) {
            g_prev[l][tok*DD + c]      = o0;
            g_prev[l][tok*DD + c + 32] = o1;
        }
    }
}

// ---------------------------------------------------------------------------
// pool + compress MLP + basin update + temps for next pass. One block, 128 thr.
__global__ void k_pool(int cursel,
                       const float* __restrict__ Wc1, const float* __restrict__ bc1,
                       const float* __restrict__ Wc2, const float* __restrict__ bc2,
                       const float* __restrict__ Wu,  const float* __restrict__ bu,
                       const float* __restrict__ W_temp, const float* __restrict__ b_temp) {
    const float* x = cursel ? g_bufB : g_bufA;
    int tid = threadIdx.x;
    __shared__ float pooled[BB][DD];
    __shared__ float h1[BB][HH];
    __shared__ float hb[BB][DD];
    __shared__ float agg[DD], comb[2*DD], nb[DD];

    int b = tid / DD, d = tid - b*DD;
    {
        float s = 0.f;
        const float* xb = x + b*TT*DD + d;
        #pragma unroll 8
        for (int t = 0; t < TT; ++t) s += xb[t*DD];
        pooled[b][d] = s * (1.f/TT);
    }
    __syncthreads();
    if (tid < BB*HH) {
        int bb = tid / HH, h = tid - bb*HH;
        float a = bc1[h];
        #pragma unroll 8
        for (int k = 0; k < DD; ++k) a = fmaf(pooled[bb][k], Wc1[h*DD + k], a);
        h1[bb][h] = tanhf(a);
    }
    __syncthreads();
    {
        float a = bc2[d];
        #pragma unroll 8
        for (int k = 0; k < HH; ++k) a = fmaf(h1[b][k], Wc2[d*HH + k], a);
        hb[b][d] = tanhf(a);
    }
    __syncthreads();
    if (tid < DD) {
        float a = 0.5f*(hb[0][tid] + hb[1][tid]);
        agg[tid]      = a;
        comb[tid]     = g_basin[tid];
        comb[DD+tid]  = a;
    }
    __syncthreads();
    if (tid < DD) {
        float a = bu[tid];
        #pragma unroll 8
        for (int k = 0; k < 2*DD; ++k) a = fmaf(Wu[tid*2*DD + k], comb[k], a);
        float g = 1.f/(1.f + expf(-a));
        nb[tid] = g_basin[tid]*(1.f - g) + agg[tid]*g;
        g_basin[tid] = nb[tid];
    }
    __syncthreads();
    if (tid < LAYERS) {
        float acc = b_temp[tid];
        #pragma unroll 8
        for (int k = 0; k < DD; ++k) acc = fmaf(W_temp[tid*DD + k], nb[k], acc);
        g_temps[tid] = 1.f/(1.f + expf(-acc)) + 0.5f;
    }
}

// ---------------------------------------------------------------------------
__global__ void k_final(int cursel, const float* __restrict__ seq,
                        const float* __restrict__ res_g, float* __restrict__ out) {
    const float* x = cursel ? g_bufB : g_bufA;
    int i = blockIdx.x*blockDim.x + threadIdx.x;
    if (i < NTOK*DD) {
        float xv = x[i];
        out[i] = xv + 0.01f * res_g[0] * (xv - seq[i]);
    }
}

// ---------------------------------------------------------------------------
extern "C" void kernel_launch(void* const* d_in, const int* in_sizes, int n_in,
                              void* d_out, int out_size) {
    const float* basin_seq    = (const float*)d_in[0];
    const float* basin_coords = (const float*)d_in[1];
    const float* W_temp       = (const float*)d_in[2];
    const float* b_temp       = (const float*)d_in[3];
    const float* res_scale    = (const float*)d_in[4];
    const float* W_fb         = (const float*)d_in[5];
    const float* b_fb         = (const float*)d_in[6];
    const float* Wc1          = (const float*)d_in[7];
    const float* bc1          = (const float*)d_in[8];
    const float* Wc2          = (const float*)d_in[9];
    const float* bc2          = (const float*)d_in[10];
    const float* Wu           = (const float*)d_in[11];
    const float* bu           = (const float*)d_in[12];
    const float* res_g        = (const float*)d_in[13];

    cudaMemcpyToSymbolAsync(g_bufA, basin_seq, NTOK*DD*sizeof(float), 0,
                            cudaMemcpyDeviceToDevice, 0);
    k_init<<<1, 64>>>(basin_coords, W_temp, b_temp, res_scale);

    int cursel = 0;
    for (int p = 0; p < 2; ++p) {
        for (int l = 0; l < LAYERS; ++l) {
            k_feat<<<NTOK/8, 128>>>(cursel, l, p > 0 ? 1 : 0, W_fb, b_fb);
            k_attn<<<NTOK/4, 256>>>(cursel, l, p == 0 ? 1 : 0);
            cursel ^= 1;
        }
        if (p == 0) {
            k_pool<<<1, 128>>>(cursel, Wc1, bc1, Wc2, bc2, Wu, bu, W_temp, b_temp);
        }
    }
    k_final<<<(NTOK*DD + 255)/256, 256>>>(cursel, basin_seq, res_g, (float*)d_out);
}

// round 3
// speedup vs baseline: 1.7112x; 1.7017x over previous
#include <cuda_runtime.h>
#include <math.h>

#define BB 2
#define TT 512
#define DD 64
#define LAYERS 4
#define HH 32
#define NTOK (BB*TT)
#define FDIM 192
#define EPSF 1e-8f
#define C2F 7.0710678e-5f   // sqrt(EPS/2)
#define C3F 3.5355339e-9f   // EPS/(2*sqrt(2))

__device__ float g_bufA[NTOK*DD];
__device__ float g_bufB[NTOK*DD];
__device__ float g_prev[LAYERS][NTOK*DD];
__device__ float g_featT[FDIM*NTOK];     // [dim][token]
__device__ float g_basin[DD];
__device__ float g_temps[LAYERS];
__device__ float g_res[LAYERS];

typedef unsigned long long u64;
typedef unsigned int u32;

// packed f32x2 helpers (sm_103a)
__device__ __forceinline__ u64 pack2(float x, float y) {
    u64 r;
    asm("mov.b64 %0, {%1, %2};" : "=l"(r) : "r"(__float_as_uint(x)), "r"(__float_as_uint(y)));
    return r;
}
__device__ __forceinline__ u64 bcast2(float x) { return pack2(x, x); }
__device__ __forceinline__ void fma2(u64& d, u64 a, u64 b) {
    asm("fma.rn.f32x2 %0, %1, %2, %0;" : "+l"(d) : "l"(a), "l"(b));
}
__device__ __forceinline__ void unpack2(u64 v, float& lo, float& hi) {
    u32 a, b;
    asm("mov.b64 {%0, %1}, %2;" : "=r"(a), "=r"(b) : "l"(v));
    lo = __uint_as_float(a); hi = __uint_as_float(b);
}

// acos for x in [-1,1], |err| ~2e-8 (A&S 4.4.45)
__device__ __forceinline__ float acos_fast(float x) {
    float ax = fabsf(x);
    float r = sqrtf(1.0f - ax);
    float p = fmaf(ax, -0.0012624911f, 0.0066700901f);
    p = fmaf(ax, p, -0.0170881256f);
    p = fmaf(ax, p, 0.0308918810f);
    p = fmaf(ax, p, -0.0501743046f);
    p = fmaf(ax, p, 0.0889789874f);
    p = fmaf(ax, p, -0.2145988016f);
    p = fmaf(ax, p, 1.5707963050f);
    float res = r * p;
    return (x < 0.f) ? (3.14159265358979f - res) : res;
}

// ---------------------------------------------------------------------------
__global__ void k_init(const float* __restrict__ basin_coords,
                       const float* __restrict__ W_temp,
                       const float* __restrict__ b_temp,
                       const float* __restrict__ res_scale) {
    int t = threadIdx.x;           // 64 threads
    __shared__ float sb[DD];
    sb[t] = basin_coords[t];
    g_basin[t] = sb[t];
    __syncthreads();
    if (t < LAYERS) {
        g_res[t] = res_scale[t];
        float acc = b_temp[t];
        #pragma unroll 8
        for (int d = 0; d < DD; ++d) acc = fmaf(W_temp[t*DD + d], sb[d], acc);
        g_temps[t] = 1.f/(1.f + expf(-acc)) + 0.5f;
    }
}

// ---------------------------------------------------------------------------
// feat: 8 tokens/block, 512 threads, thread = (tok, d). Gated GEMV via smem
// with pad-132 (conflict-free float4). Then simplex + factored features.
__global__ void __launch_bounds__(512) k_feat(int cursel, int l, int gated,
        const float* __restrict__ W_fb, const float* __restrict__ b_fb) {
    float* x = cursel ? g_bufB : g_bufA;
    int tid = threadIdx.x;
    int tok0 = blockIdx.x * 8;
    int tok = tid >> 6, d = tid & 63;

    __shared__ float sW[64*132];
    __shared__ float sx[8][64], spv[8][64];
    __shared__ float sred[8][2];

    float xv;
    if (gated) {
        sx[tok][d]  = x[tok0*64 + tid];
        spv[tok][d] = g_prev[l][tok0*64 + tid];
        #pragma unroll
        for (int i = tid; i < 64*128; i += 512)
            sW[(i>>7)*132 + (i&127)] = W_fb[l*64*128 + i];
        __syncthreads();
        float acc = b_fb[l*64 + d];
        const float4* Wr = (const float4*)&sW[d*132];
        const float4* xr = (const float4*)&sx[tok][0];
        const float4* pr = (const float4*)&spv[tok][0];
        #pragma unroll
        for (int q = 0; q < 16; ++q) {
            float4 wv = Wr[q], vv = xr[q];
            acc += wv.x*vv.x + wv.y*vv.y + wv.z*vv.z + wv.w*vv.w;
        }
        #pragma unroll
        for (int q = 0; q < 16; ++q) {
            float4 wv = Wr[16+q], vv = pr[q];
            acc += wv.x*vv.x + wv.y*vv.y + wv.z*vv.z + wv.w*vv.w;
        }
        float g = 1.f/(1.f + __expf(-acc));
        xv = sx[tok][d]*g + spv[tok][d]*(1.f-g);
        x[tok0*64 + tid] = xv;
    } else {
        xv = x[tok0*64 + tid];
    }

    // stable softplus
    float sp = fmaxf(xv, 0.f) + log1pf(__expf(-fabsf(xv)));

    int half = (tid >> 5) & 1;
    // first normalization
    float v = sp;
    #pragma unroll
    for (int o = 16; o; o >>= 1) v += __shfl_xor_sync(0xffffffffu, v, o);
    if ((tid & 31) == 0) sred[tok][half] = v;
    __syncthreads();
    float s1 = sred[tok][0] + sred[tok][1] + EPSF;
    float s = fmaxf(sp/s1, EPSF);
    __syncthreads();
    // second normalization
    v = s;
    #pragma unroll
    for (int o = 16; o; o >>= 1) v += __shfl_xor_sync(0xffffffffu, v, o);
    if ((tid & 31) == 0) sred[tok][half] = v;
    __syncthreads();
    float s2 = sred[tok][0] + sred[tok][1] + EPSF;
    float p = s/s2;

    float u = sqrtf(p);
    int gt = tok0 + tok;
    g_featT[d*NTOK + gt]        = u;
    g_featT[(64+d)*NTOK + gt]   = C2F/u;
    g_featT[(128+d)*NTOK + gt]  = C3F/(p*u);
}

// ---------------------------------------------------------------------------
// attention: 8 rows/block, 512 threads (16 warps), grid=128. Warp w owns
// j = w*32 + lane. f32x2 packed accumulators over row-pairs. No-max softmax
// (logits in [-12.6, 0]).
__global__ void __launch_bounds__(512)
k_attn(int cursel, int l, int snap) {
    const float* xin = cursel ? g_bufB : g_bufA;
    float*       xout = cursel ? g_bufA : g_bufB;

    int blk = blockIdx.x;
    int b = blk >> 6;
    int rowBase = (blk & 63) << 3;      // *8
    int tid = threadIdx.x, w = tid >> 5, c = tid & 31;

    __shared__ __align__(16) float rfT[FDIM][8];     // [dim][row], t-segment negated
    __shared__ __align__(16) float2 LeP[4][TT];      // e for row-pairs
    __shared__ float wSum[16][8];
    __shared__ __align__(16) float2 wF0[8][4][32];   // partial F (dims 0-31), row-pairs
    __shared__ __align__(16) float2 wF1[8][4][32];   // partial F (dims 32-63)

    float nInvT = -1.f / fmaxf(g_temps[l], 1e-6f);

    // stage row features (transposed), negate t-segment
    for (int idx = tid; idx < 8*FDIM; idx += 512) {
        int dd = idx >> 3, r = idx & 7;
        float fv = g_featT[dd*NTOK + b*TT + rowBase + r];
        rfT[dd][r] = (dd < 128) ? fv : -fv;
    }
    __syncthreads();

    // phase 1: 192-dim dots for this lane's j, 8 rows via 4 packed accumulators
    int jl = w*32 + c;
    const float* fb = g_featT + b*TT + jl;
    u64 acc[4] = {0ull, 0ull, 0ull, 0ull};
    #pragma unroll 1
    for (int dd0 = 0; dd0 < FDIM; dd0 += 8) {
        float jv[8];
        #pragma unroll
        for (int u = 0; u < 8; ++u) jv[u] = fb[(dd0+u)*NTOK];
        #pragma unroll
        for (int u = 0; u < 8; ++u) {
            const ulonglong2* rp = (const ulonglong2*)&rfT[dd0+u][0];
            ulonglong2 rAB = rp[0];
            ulonglong2 rCD = rp[1];
            u64 jb = bcast2(jv[u]);
            fma2(acc[0], rAB.x, jb);
            fma2(acc[1], rAB.y, jb);
            fma2(acc[2], rCD.x, jb);
            fma2(acc[3], rCD.y, jb);
        }
    }

    // e = exp(2*acos(clip(inner))*nInvT); store row-pairs; warp row-sums
    float e[8];
    #pragma unroll
    for (int q = 0; q < 4; ++q) {
        float i0, i1;
        unpack2(acc[q], i0, i1);
        i0 = fminf(fmaxf(i0, -1.f + 1e-6f), 1.f - 1e-6f);
        i1 = fminf(fmaxf(i1, -1.f + 1e-6f), 1.f - 1e-6f);
        e[2*q]   = __expf(2.f*acos_fast(i0)*nInvT);
        e[2*q+1] = __expf(2.f*acos_fast(i1)*nInvT);
        ((u64*)&LeP[q][0])[jl] = pack2(e[2*q], e[2*q+1]);
    }
    #pragma unroll
    for (int r = 0; r < 8; ++r) {
        float sv = e[r];
        #pragma unroll
        for (int o = 16; o; o >>= 1) sv += __shfl_xor_sync(0xffffffffu, sv, o);
        if (c == 0) wSum[w][r] = sv;
    }
    __syncthreads();

    // phase 3: value accumulation by warps 0..7, warp w8 owns j in [w8*64, +64)
    if (w < 8) {
        u64 f0p[4] = {0ull,0ull,0ull,0ull};
        u64 f1p[4] = {0ull,0ull,0ull,0ull};
        const float* xb = xin + b*TT*DD;
        #pragma unroll 4
        for (int jj = 0; jj < 64; ++jj) {
            int j = w*64 + jj;
            float xv0 = xb[j*DD + c];
            float xv1 = xb[j*DD + c + 32];
            u64 x0 = bcast2(xv0), x1 = bcast2(xv1);
            #pragma unroll
            for (int q = 0; q < 4; ++q) {
                u64 ep = ((const u64*)&LeP[q][0])[j];
                fma2(f0p[q], ep, x0);
                fma2(f1p[q], ep, x1);
            }
        }
        #pragma unroll
        for (int q = 0; q < 4; ++q) {
            ((u64*)&wF0[w][q][0])[c] = f0p[q];
            ((u64*)&wF1[w][q][0])[c] = f1p[q];
        }
    }
    __syncthreads();

    // merge: thread = (row r, dim d)
    {
        int r = tid >> 6, d = tid & 63;
        int rp = r >> 1, sel = r & 1;
        float F = 0.f, S = 0.f;
        #pragma unroll
        for (int ww = 0; ww < 8; ++ww) {
            const float2& fp = (d < 32) ? wF0[ww][rp][d] : wF1[ww][rp][d-32];
            F += sel ? fp.y : fp.x;
        }
        #pragma unroll
        for (int ww = 0; ww < 16; ++ww) S += wSum[ww][r];
        int tok = b*TT + rowBase + r;
        float rs = g_res[l];
        float xv = xin[tok*DD + d];
        float o = xv + rs*(F/S - xv);
        xout[tok*DD + d] = o;
        if (snap) g_prev[l][tok*DD + d] = o;
    }
}

// ---------------------------------------------------------------------------
// pool + compress MLP + basin update + temps. One block, 512 threads.
__global__ void __launch_bounds__(512) k_pool(int cursel,
                       const float* __restrict__ Wc1, const float* __restrict__ bc1,
                       const float* __restrict__ Wc2, const float* __restrict__ bc2,
                       const float* __restrict__ Wu,  const float* __restrict__ bu,
                       const float* __restrict__ W_temp, const float* __restrict__ b_temp) {
    const float* x = cursel ? g_bufB : g_bufA;
    int tid = threadIdx.x;
    __shared__ float part[4][BB*DD];
    __shared__ float pooled[BB][DD];
    __shared__ float h1[BB][HH];
    __shared__ float hb[BB][DD];
    __shared__ float agg[DD], comb[2*DD], nb[DD];

    {
        int it = tid & 127, ch = tid >> 7;
        int b = it >> 6, d = it & 63;
        float s = 0.f;
        const float* xb = x + b*TT*DD + d;
        #pragma unroll 8
        for (int t = ch*128; t < ch*128 + 128; ++t) s += xb[t*DD];
        part[ch][it] = s;
    }
    __syncthreads();
    if (tid < 128) {
        pooled[tid>>6][tid&63] =
            (part[0][tid] + part[1][tid] + part[2][tid] + part[3][tid]) * (1.f/TT);
    }
    __syncthreads();
    if (tid < BB*HH) {
        int bb = tid / HH, h = tid - bb*HH;
        float a = bc1[h];
        #pragma unroll 8
        for (int k = 0; k < DD; ++k) a = fmaf(pooled[bb][k], Wc1[h*DD + k], a);
        h1[bb][h] = tanhf(a);
    }
    __syncthreads();
    if (tid < 128) {
        int b = tid >> 6, d = tid & 63;
        float a = bc2[d];
        #pragma unroll 8
        for (int k = 0; k < HH; ++k) a = fmaf(h1[b][k], Wc2[d*HH + k], a);
        hb[b][d] = tanhf(a);
    }
    __syncthreads();
    if (tid < DD) {
        float a = 0.5f*(hb[0][tid] + hb[1][tid]);
        agg[tid]      = a;
        comb[tid]     = g_basin[tid];
        comb[DD+tid]  = a;
    }
    __syncthreads();
    if (tid < DD) {
        float a = bu[tid];
        #pragma unroll 8
        for (int k = 0; k < 2*DD; ++k) a = fmaf(Wu[tid*2*DD + k], comb[k], a);
        float g = 1.f/(1.f + expf(-a));
        nb[tid] = g_basin[tid]*(1.f - g) + agg[tid]*g;
        g_basin[tid] = nb[tid];
    }
    __syncthreads();
    if (tid < LAYERS) {
        float acc = b_temp[tid];
        #pragma unroll 8
        for (int k = 0; k < DD; ++k) acc = fmaf(W_temp[tid*DD + k], nb[k], acc);
        g_temps[tid] = 1.f/(1.f + expf(-acc)) + 0.5f;
    }
}

// ---------------------------------------------------------------------------
__global__ void k_final(int cursel, const float* __restrict__ seq,
                        const float* __restrict__ res_g, float* __restrict__ out) {
    const float* x = cursel ? g_bufB : g_bufA;
    int i = blockIdx.x*blockDim.x + threadIdx.x;
    if (i < NTOK*DD) {
        float xv = x[i];
        out[i] = xv + 0.01f * res_g[0] * (xv - seq[i]);
    }
}

// ---------------------------------------------------------------------------
extern "C" void kernel_launch(void* const* d_in, const int* in_sizes, int n_in,
                              void* d_out, int out_size) {
    const float* basin_seq    = (const float*)d_in[0];
    const float* basin_coords = (const float*)d_in[1];
    const float* W_temp       = (const float*)d_in[2];
    const float* b_temp       = (const float*)d_in[3];
    const float* res_scale    = (const float*)d_in[4];
    const float* W_fb         = (const float*)d_in[5];
    const float* b_fb         = (const float*)d_in[6];
    const float* Wc1          = (const float*)d_in[7];
    const float* bc1          = (const float*)d_in[8];
    const float* Wc2          = (const float*)d_in[9];
    const float* bc2          = (const float*)d_in[10];
    const float* Wu           = (const float*)d_in[11];
    const float* bu           = (const float*)d_in[12];
    const float* res_g        = (const float*)d_in[13];

    cudaMemcpyToSymbolAsync(g_bufA, basin_seq, NTOK*DD*sizeof(float), 0,
                            cudaMemcpyDeviceToDevice, 0);
    k_init<<<1, 64>>>(basin_coords, W_temp, b_temp, res_scale);

    int cursel = 0;
    for (int p = 0; p < 2; ++p) {
        for (int l = 0; l < LAYERS; ++l) {
            k_feat<<<NTOK/8, 512>>>(cursel, l, p > 0 ? 1 : 0, W_fb, b_fb);
            k_attn<<<NTOK/8, 512>>>(cursel, l, p == 0 ? 1 : 0);
            cursel ^= 1;
        }
        if (p == 0) {
            k_pool<<<1, 512>>>(cursel, Wc1, bc1, Wc2, bc2, Wu, bu, W_temp, b_temp);
        }
    }
    k_final<<<(NTOK*DD + 255)/256, 256>>>(cursel, basin_seq, res_g, (float*)d_out);
}

// round 4
// speedup vs baseline: 2.2977x; 1.3428x over previous
#include <cuda_runtime.h>
#include <math.h>

#define BB 2
#define TT 512
#define DD 64
#define LAYERS 4
#define HH 32
#define NTOK (BB*TT)
#define FDIM 192
#define EPSF 1e-8f
#define C2F 7.0710678e-5f   // sqrt(EPS/2)
#define C3F 3.5355339e-9f   // EPS/(2*sqrt(2))

__device__ float g_bufA[NTOK*DD];
__device__ float g_bufB[NTOK*DD];
__device__ float g_prev[LAYERS][NTOK*DD];
__device__ float g_featT[FDIM*NTOK];     // [dim][token]
__device__ float g_basin[DD];
__device__ float g_temps[LAYERS];
__device__ float g_res[LAYERS];

typedef unsigned long long u64;
typedef unsigned int u32;

__device__ __forceinline__ u64 pack2(float x, float y) {
    u64 r;
    asm("mov.b64 %0, {%1, %2};" : "=l"(r) : "r"(__float_as_uint(x)), "r"(__float_as_uint(y)));
    return r;
}
__device__ __forceinline__ u64 bcast2(float x) { return pack2(x, x); }
__device__ __forceinline__ void fma2(u64& d, u64 a, u64 b) {
    asm("fma.rn.f32x2 %0, %1, %2, %0;" : "+l"(d) : "l"(a), "l"(b));
}
__device__ __forceinline__ void unpack2(u64 v, float& lo, float& hi) {
    u32 a, b;
    asm("mov.b64 {%0, %1}, %2;" : "=r"(a), "=r"(b) : "l"(v));
    lo = __uint_as_float(a); hi = __uint_as_float(b);
}

// acos for x in [-1,1], |err| ~2e-8 (A&S 4.4.45)
__device__ __forceinline__ float acos_fast(float x) {
    float ax = fabsf(x);
    float r = sqrtf(1.0f - ax);
    float p = fmaf(ax, -0.0012624911f, 0.0066700901f);
    p = fmaf(ax, p, -0.0170881256f);
    p = fmaf(ax, p, 0.0308918810f);
    p = fmaf(ax, p, -0.0501743046f);
    p = fmaf(ax, p, 0.0889789874f);
    p = fmaf(ax, p, -0.2145988016f);
    p = fmaf(ax, p, 1.5707963050f);
    float res = r * p;
    return (x < 0.f) ? (3.14159265358979f - res) : res;
}

// ---------------------------------------------------------------------------
__global__ void __launch_bounds__(512) k_copy(const float* __restrict__ src) {
    int i = blockIdx.x*512 + threadIdx.x;
    g_bufA[i] = src[i];
}

// ---------------------------------------------------------------------------
__global__ void k_init(const float* __restrict__ basin_coords,
                       const float* __restrict__ W_temp,
                       const float* __restrict__ b_temp,
                       const float* __restrict__ res_scale) {
    int t = threadIdx.x;           // 64 threads
    __shared__ float sb[DD];
    sb[t] = basin_coords[t];
    g_basin[t] = sb[t];
    __syncthreads();
    if (t < LAYERS) {
        g_res[t] = res_scale[t];
        float acc = b_temp[t];
        #pragma unroll 8
        for (int d = 0; d < DD; ++d) acc = fmaf(W_temp[t*DD + d], sb[d], acc);
        g_temps[t] = 1.f/(1.f + expf(-acc)) + 0.5f;
    }
}

// ---------------------------------------------------------------------------
// feat: 16 tokens/block (grid 64), warp = token, lane c owns dims c, c+32.
// Warp-local reductions (no block syncs in normalize path). Transposed
// feature store staged through smem (pad 17) then written coalesced.
__global__ void __launch_bounds__(512) k_feat(int cursel, int l, int gated,
        const float* __restrict__ W_fb, const float* __restrict__ b_fb) {
    float* x = cursel ? g_bufB : g_bufA;
    int tid = threadIdx.x;
    int wid = tid >> 5, c = tid & 31;
    int tok0 = blockIdx.x * 16;
    int tok = tok0 + wid;

    __shared__ float sW[64*132];
    __shared__ float sx[16][64], spv[16][64];
    __shared__ float sfeat[FDIM][17];

    float xn0, xn1;
    if (gated) {
        for (int i = tid; i < 16*64; i += 512) {
            sx[i>>6][i&63]  = x[tok0*64 + i];
            spv[i>>6][i&63] = g_prev[l][tok0*64 + i];
        }
        #pragma unroll
        for (int i = tid; i < 64*128; i += 512)
            sW[(i>>7)*132 + (i&127)] = W_fb[l*64*128 + i];
        __syncthreads();
        float a0 = b_fb[l*64 + c], a1 = b_fb[l*64 + c + 32];
        const float4* W0 = (const float4*)&sW[c*132];
        const float4* W1 = (const float4*)&sW[(c+32)*132];
        const float4* xr = (const float4*)&sx[wid][0];
        const float4* pr = (const float4*)&spv[wid][0];
        #pragma unroll
        for (int q = 0; q < 16; ++q) {
            float4 xv = xr[q], w0 = W0[q], w1 = W1[q];
            a0 += w0.x*xv.x + w0.y*xv.y + w0.z*xv.z + w0.w*xv.w;
            a1 += w1.x*xv.x + w1.y*xv.y + w1.z*xv.z + w1.w*xv.w;
        }
        #pragma unroll
        for (int q = 0; q < 16; ++q) {
            float4 pv = pr[q], w0 = W0[16+q], w1 = W1[16+q];
            a0 += w0.x*pv.x + w0.y*pv.y + w0.z*pv.z + w0.w*pv.w;
            a1 += w1.x*pv.x + w1.y*pv.y + w1.z*pv.z + w1.w*pv.w;
        }
        float g0 = 1.f/(1.f + __expf(-a0));
        float g1 = 1.f/(1.f + __expf(-a1));
        float xv0 = sx[wid][c],    pv0 = spv[wid][c];
        float xv1 = sx[wid][c+32], pv1 = spv[wid][c+32];
        xn0 = xv0*g0 + pv0*(1.f-g0);
        xn1 = xv1*g1 + pv1*(1.f-g1);
        x[tok*64 + c]      = xn0;
        x[tok*64 + c + 32] = xn1;
    } else {
        xn0 = x[tok*64 + c];
        xn1 = x[tok*64 + c + 32];
    }

    // stable softplus
    float sp0 = fmaxf(xn0, 0.f) + log1pf(__expf(-fabsf(xn0)));
    float sp1 = fmaxf(xn1, 0.f) + log1pf(__expf(-fabsf(xn1)));

    // first normalization (warp-local: 64 dims live in this warp)
    float v = sp0 + sp1;
    #pragma unroll
    for (int o = 16; o; o >>= 1) v += __shfl_xor_sync(0xffffffffu, v, o);
    float s1 = v + EPSF;
    float q0 = fmaxf(sp0/s1, EPSF), q1 = fmaxf(sp1/s1, EPSF);
    // second normalization
    v = q0 + q1;
    #pragma unroll
    for (int o = 16; o; o >>= 1) v += __shfl_xor_sync(0xffffffffu, v, o);
    float s2 = v + EPSF;
    float p0 = q0/s2, p1 = q1/s2;

    float u0 = sqrtf(p0), u1 = sqrtf(p1);
    sfeat[c][wid]        = u0;
    sfeat[64+c][wid]     = C2F/u0;
    sfeat[128+c][wid]    = C3F/(p0*u0);
    sfeat[c+32][wid]     = u1;
    sfeat[64+c+32][wid]  = C2F/u1;
    sfeat[128+c+32][wid] = C3F/(p1*u1);
    __syncthreads();

    // coalesced transposed store: dims major, 16 tokens contiguous
    #pragma unroll
    for (int i = tid; i < FDIM*16; i += 512) {
        int dim = i >> 4, t = i & 15;
        g_featT[dim*NTOK + tok0 + t] = sfeat[dim][t];
    }
}

// ---------------------------------------------------------------------------
// attention: 8 rows/block, 512 threads (16 warps), grid=128.
// Phase1: warp w owns j = w*32+c; prefetched feature loads, f32x2 row-pair accs.
// Phase3: all 16 warps, 32 j's each, prefetched value loads.
__global__ void __launch_bounds__(512)
k_attn(int cursel, int l, int snap) {
    const float* xin = cursel ? g_bufB : g_bufA;
    float*       xout = cursel ? g_bufA : g_bufB;

    int blk = blockIdx.x;
    int b = blk >> 6;
    int rowBase = (blk & 63) << 3;
    int tid = threadIdx.x, w = tid >> 5, c = tid & 31;

    __shared__ __align__(16) float rfT[FDIM][8];     // [dim][row], t-seg negated
    __shared__ __align__(16) float2 LeP[4][TT];      // e for row-pairs
    __shared__ float wSum[16][8];
    __shared__ __align__(16) float2 wF0[16][4][32];  // partials dims 0-31
    __shared__ __align__(16) float2 wF1[16][4][32];  // partials dims 32-63

    float nInvT = -1.f / fmaxf(g_temps[l], 1e-6f);

    for (int idx = tid; idx < 8*FDIM; idx += 512) {
        int dd = idx >> 3, r = idx & 7;
        float fv = g_featT[dd*NTOK + b*TT + rowBase + r];
        rfT[dd][r] = (dd < 128) ? fv : -fv;
    }
    __syncthreads();

    // phase 1: 192-dot, 8 rows via 4 packed accumulators, prefetched
    int jl = w*32 + c;
    const float* fb = g_featT + b*TT + jl;
    u64 acc[4] = {0ull, 0ull, 0ull, 0ull};
    float jv[8], jvn[8];
    #pragma unroll
    for (int u = 0; u < 8; ++u) jv[u] = fb[u*NTOK];
    #pragma unroll 1
    for (int dd0 = 0; dd0 < FDIM; dd0 += 8) {
        if (dd0 + 8 < FDIM) {
            #pragma unroll
            for (int u = 0; u < 8; ++u) jvn[u] = fb[(dd0+8+u)*NTOK];
        }
        #pragma unroll
        for (int u = 0; u < 8; ++u) {
            const ulonglong2* rp = (const ulonglong2*)&rfT[dd0+u][0];
            ulonglong2 rAB = rp[0];
            ulonglong2 rCD = rp[1];
            u64 jb = bcast2(jv[u]);
            fma2(acc[0], rAB.x, jb);
            fma2(acc[1], rAB.y, jb);
            fma2(acc[2], rCD.x, jb);
            fma2(acc[3], rCD.y, jb);
        }
        #pragma unroll
        for (int u = 0; u < 8; ++u) jv[u] = jvn[u];
    }

    // e = exp(2*acos(clip)*nInvT); store row-pairs; warp row-sums (no-max: logits<=0)
    float e[8];
    #pragma unroll
    for (int q = 0; q < 4; ++q) {
        float i0, i1;
        unpack2(acc[q], i0, i1);
        i0 = fminf(fmaxf(i0, -1.f + 1e-6f), 1.f - 1e-6f);
        i1 = fminf(fmaxf(i1, -1.f + 1e-6f), 1.f - 1e-6f);
        e[2*q]   = __expf(2.f*acos_fast(i0)*nInvT);
        e[2*q+1] = __expf(2.f*acos_fast(i1)*nInvT);
        ((u64*)&LeP[q][0])[jl] = pack2(e[2*q], e[2*q+1]);
    }
    #pragma unroll
    for (int r = 0; r < 8; ++r) {
        float sv = e[r];
        #pragma unroll
        for (int o = 16; o; o >>= 1) sv += __shfl_xor_sync(0xffffffffu, sv, o);
        if (c == 0) wSum[w][r] = sv;
    }
    __syncthreads();

    // phase 3: value accumulation, all 16 warps, 32 j's each, prefetched
    {
        u64 f0p[4] = {0ull,0ull,0ull,0ull};
        u64 f1p[4] = {0ull,0ull,0ull,0ull};
        const float* xb = xin + b*TT*DD;
        int j0 = w*32;
        float xv0 = xb[j0*DD + c], xv1 = xb[j0*DD + c + 32];
        #pragma unroll 4
        for (int jj = 0; jj < 32; ++jj) {
            int j = j0 + jj;
            float nx0 = 0.f, nx1 = 0.f;
            if (jj < 31) {
                nx0 = xb[(j+1)*DD + c];
                nx1 = xb[(j+1)*DD + c + 32];
            }
            u64 x0 = bcast2(xv0), x1 = bcast2(xv1);
            #pragma unroll
            for (int q = 0; q < 4; ++q) {
                u64 ep = ((const u64*)&LeP[q][0])[j];
                fma2(f0p[q], ep, x0);
                fma2(f1p[q], ep, x1);
            }
            xv0 = nx0; xv1 = nx1;
        }
        #pragma unroll
        for (int q = 0; q < 4; ++q) {
            ((u64*)&wF0[w][q][0])[c] = f0p[q];
            ((u64*)&wF1[w][q][0])[c] = f1p[q];
        }
    }
    __syncthreads();

    // merge: thread = (row r, dim d)
    {
        int r = tid >> 6, d = tid & 63;
        int rp = r >> 1, sel = r & 1;
        float F = 0.f, S = 0.f;
        #pragma unroll
        for (int ww = 0; ww < 16; ++ww) {
            const float2& fp = (d < 32) ? wF0[ww][rp][d] : wF1[ww][rp][d-32];
            F += sel ? fp.y : fp.x;
            S += wSum[ww][r];
        }
        int tok = b*TT + rowBase + r;
        float rs = g_res[l];
        float xv = xin[tok*DD + d];
        float o = xv + rs*(F/S - xv);
        xout[tok*DD + d] = o;
        if (snap) g_prev[l][tok*DD + d] = o;
    }
}

// ---------------------------------------------------------------------------
__global__ void __launch_bounds__(512) k_pool(int cursel,
                       const float* __restrict__ Wc1, const float* __restrict__ bc1,
                       const float* __restrict__ Wc2, const float* __restrict__ bc2,
                       const float* __restrict__ Wu,  const float* __restrict__ bu,
                       const float* __restrict__ W_temp, const float* __restrict__ b_temp) {
    const float* x = cursel ? g_bufB : g_bufA;
    int tid = threadIdx.x;
    __shared__ float part[4][BB*DD];
    __shared__ float pooled[BB][DD];
    __shared__ float h1[BB][HH];
    __shared__ float hb[BB][DD];
    __shared__ float agg[DD], comb[2*DD], nb[DD];

    {
        int it = tid & 127, ch = tid >> 7;
        int b = it >> 6, d = it & 63;
        float s = 0.f;
        const float* xb = x + b*TT*DD + d;
        #pragma unroll 8
        for (int t = ch*128; t < ch*128 + 128; ++t) s += xb[t*DD];
        part[ch][it] = s;
    }
    __syncthreads();
    if (tid < 128) {
        pooled[tid>>6][tid&63] =
            (part[0][tid] + part[1][tid] + part[2][tid] + part[3][tid]) * (1.f/TT);
    }
    __syncthreads();
    if (tid < BB*HH) {
        int bb = tid / HH, h = tid - bb*HH;
        float a = bc1[h];
        #pragma unroll 8
        for (int k = 0; k < DD; ++k) a = fmaf(pooled[bb][k], Wc1[h*DD + k], a);
        h1[bb][h] = tanhf(a);
    }
    __syncthreads();
    if (tid < 128) {
        int b = tid >> 6, d = tid & 63;
        float a = bc2[d];
        #pragma unroll 8
        for (int k = 0; k < HH; ++k) a = fmaf(h1[b][k], Wc2[d*HH + k], a);
        hb[b][d] = tanhf(a);
    }
    __syncthreads();
    if (tid < DD) {
        float a = 0.5f*(hb[0][tid] + hb[1][tid]);
        agg[tid]      = a;
        comb[tid]     = g_basin[tid];
        comb[DD+tid]  = a;
    }
    __syncthreads();
    if (tid < DD) {
        float a = bu[tid];
        #pragma unroll 8
        for (int k = 0; k < 2*DD; ++k) a = fmaf(Wu[tid*2*DD + k], comb[k], a);
        float g = 1.f/(1.f + expf(-a));
        nb[tid] = g_basin[tid]*(1.f - g) + agg[tid]*g;
        g_basin[tid] = nb[tid];
    }
    __syncthreads();
    if (tid < LAYERS) {
        float acc = b_temp[tid];
        #pragma unroll 8
        for (int k = 0; k < DD; ++k) acc = fmaf(W_temp[tid*DD + k], nb[k], acc);
        g_temps[tid] = 1.f/(1.f + expf(-acc)) + 0.5f;
    }
}

// ---------------------------------------------------------------------------
__global__ void k_final(int cursel, const float* __restrict__ seq,
                        const float* __restrict__ res_g, float* __restrict__ out) {
    const float* x = cursel ? g_bufB : g_bufA;
    int i = blockIdx.x*blockDim.x + threadIdx.x;
    if (i < NTOK*DD) {
        float xv = x[i];
        out[i] = xv + 0.01f * res_g[0] * (xv - seq[i]);
    }
}

// ---------------------------------------------------------------------------
extern "C" void kernel_launch(void* const* d_in, const int* in_sizes, int n_in,
                              void* d_out, int out_size) {
    const float* basin_seq    = (const float*)d_in[0];
    const float* basin_coords = (const float*)d_in[1];
    const float* W_temp       = (const float*)d_in[2];
    const float* b_temp       = (const float*)d_in[3];
    const float* res_scale    = (const float*)d_in[4];
    const float* W_fb         = (const float*)d_in[5];
    const float* b_fb         = (const float*)d_in[6];
    const float* Wc1          = (const float*)d_in[7];
    const float* bc1          = (const float*)d_in[8];
    const float* Wc2          = (const float*)d_in[9];
    const float* bc2          = (const float*)d_in[10];
    const float* Wu           = (const float*)d_in[11];
    const float* bu           = (const float*)d_in[12];
    const float* res_g        = (const float*)d_in[13];

    k_copy<<<NTOK*DD/512, 512>>>(basin_seq);
    k_init<<<1, 64>>>(basin_coords, W_temp, b_temp, res_scale);

    int cursel = 0;
    for (int p = 0; p < 2; ++p) {
        for (int l = 0; l < LAYERS; ++l) {
            k_feat<<<NTOK/16, 512>>>(cursel, l, p > 0 ? 1 : 0, W_fb, b_fb);
            k_attn<<<NTOK/8, 512>>>(cursel, l, p == 0 ? 1 : 0);
            cursel ^= 1;
        }
        if (p == 0) {
            k_pool<<<1, 512>>>(cursel, Wc1, bc1, Wc2, bc2, Wu, bu, W_temp, b_temp);
        }
    }
    k_final<<<(NTOK*DD + 255)/256, 256>>>(cursel, basin_seq, res_g, (float*)d_out);
}

// round 5
// speedup vs baseline: 2.7121x; 1.1803x over previous
#include <cuda_runtime.h>
#include <math.h>

#define BB 2
#define TT 512
#define DD 64
#define LAYERS 4
#define HH 32
#define NTOK (BB*TT)
#define FDIM 128            // u (64) + v (64); t-term dropped (negligible: O(eps^2))
#define EPSF 1e-8f
#define C2F 7.0710678e-5f   // sqrt(EPS/2)

__device__ float g_bufA[NTOK*DD];
__device__ float g_bufB[NTOK*DD];
__device__ float g_prev[LAYERS][NTOK*DD];
__device__ float2 g_featP[(FDIM/2)*NTOK];   // [dimpair][token] packed
__device__ float g_basin[DD];
__device__ float g_temps[LAYERS];
__device__ float g_res[LAYERS];

typedef unsigned long long u64;
typedef unsigned int u32;

__device__ __forceinline__ u64 pack2(float x, float y) {
    u64 r;
    asm("mov.b64 %0, {%1, %2};" : "=l"(r) : "r"(__float_as_uint(x)), "r"(__float_as_uint(y)));
    return r;
}
__device__ __forceinline__ u64 bcast2(float x) { return pack2(x, x); }
__device__ __forceinline__ void fma2(u64& d, u64 a, u64 b) {
    asm("fma.rn.f32x2 %0, %1, %2, %0;" : "+l"(d) : "l"(a), "l"(b));
}
__device__ __forceinline__ void unpack2(u64 v, float& lo, float& hi) {
    u32 a, b;
    asm("mov.b64 {%0, %1}, %2;" : "=r"(a), "=r"(b) : "l"(v));
    lo = __uint_as_float(a); hi = __uint_as_float(b);
}

// acos for x in [-1,1], |err| ~2e-8 (A&S 4.4.45)
__device__ __forceinline__ float acos_fast(float x) {
    float ax = fabsf(x);
    float r = sqrtf(1.0f - ax);
    float p = fmaf(ax, -0.0012624911f, 0.0066700901f);
    p = fmaf(ax, p, -0.0170881256f);
    p = fmaf(ax, p, 0.0308918810f);
    p = fmaf(ax, p, -0.0501743046f);
    p = fmaf(ax, p, 0.0889789874f);
    p = fmaf(ax, p, -0.2145988016f);
    p = fmaf(ax, p, 1.5707963050f);
    float res = r * p;
    return (x < 0.f) ? (3.14159265358979f - res) : res;
}

// ---------------------------------------------------------------------------
__global__ void __launch_bounds__(512) k_copy(const float* __restrict__ src) {
    int i = blockIdx.x*512 + threadIdx.x;
    g_bufA[i] = src[i];
}

// ---------------------------------------------------------------------------
__global__ void k_init(const float* __restrict__ basin_coords,
                       const float* __restrict__ W_temp,
                       const float* __restrict__ b_temp,
                       const float* __restrict__ res_scale) {
    int t = threadIdx.x;           // 64 threads
    __shared__ float sb[DD];
    sb[t] = basin_coords[t];
    g_basin[t] = sb[t];
    __syncthreads();
    if (t < LAYERS) {
        g_res[t] = res_scale[t];
        float acc = b_temp[t];
        #pragma unroll 8
        for (int d = 0; d < DD; ++d) acc = fmaf(W_temp[t*DD + d], sb[d], acc);
        g_temps[t] = 1.f/(1.f + expf(-acc)) + 0.5f;
    }
}

// ---------------------------------------------------------------------------
// feat: 16 tokens/block (grid 64), warp = token, lane c owns dims c, c+32.
// Feature layout (per token, 128 dims): u[0..63], v[64..127]. Stored packed
// as float2 per dim-pair, token-major within a pair.
__global__ void __launch_bounds__(512) k_feat(int cursel, int l, int gated,
        const float* __restrict__ W_fb, const float* __restrict__ b_fb) {
    float* x = cursel ? g_bufB : g_bufA;
    int tid = threadIdx.x;
    int wid = tid >> 5, c = tid & 31;
    int tok0 = blockIdx.x * 16;
    int tok = tok0 + wid;

    __shared__ float sW[64*132];
    __shared__ float sx[16][64], spv[16][64];
    __shared__ float sfeat[FDIM][17];

    float xn0, xn1;
    if (gated) {
        for (int i = tid; i < 16*64; i += 512) {
            sx[i>>6][i&63]  = x[tok0*64 + i];
            spv[i>>6][i&63] = g_prev[l][tok0*64 + i];
        }
        #pragma unroll
        for (int i = tid; i < 64*128; i += 512)
            sW[(i>>7)*132 + (i&127)] = W_fb[l*64*128 + i];
        __syncthreads();
        float a0 = b_fb[l*64 + c], a1 = b_fb[l*64 + c + 32];
        const float4* W0 = (const float4*)&sW[c*132];
        const float4* W1 = (const float4*)&sW[(c+32)*132];
        const float4* xr = (const float4*)&sx[wid][0];
        const float4* pr = (const float4*)&spv[wid][0];
        #pragma unroll
        for (int q = 0; q < 16; ++q) {
            float4 xv = xr[q], w0 = W0[q], w1 = W1[q];
            a0 += w0.x*xv.x + w0.y*xv.y + w0.z*xv.z + w0.w*xv.w;
            a1 += w1.x*xv.x + w1.y*xv.y + w1.z*xv.z + w1.w*xv.w;
        }
        #pragma unroll
        for (int q = 0; q < 16; ++q) {
            float4 pv = pr[q], w0 = W0[16+q], w1 = W1[16+q];
            a0 += w0.x*pv.x + w0.y*pv.y + w0.z*pv.z + w0.w*pv.w;
            a1 += w1.x*pv.x + w1.y*pv.y + w1.z*pv.z + w1.w*pv.w;
        }
        float g0 = 1.f/(1.f + __expf(-a0));
        float g1 = 1.f/(1.f + __expf(-a1));
        float xv0 = sx[wid][c],    pv0 = spv[wid][c];
        float xv1 = sx[wid][c+32], pv1 = spv[wid][c+32];
        xn0 = xv0*g0 + pv0*(1.f-g0);
        xn1 = xv1*g1 + pv1*(1.f-g1);
        x[tok*64 + c]      = xn0;
        x[tok*64 + c + 32] = xn1;
    } else {
        xn0 = x[tok*64 + c];
        xn1 = x[tok*64 + c + 32];
    }

    // stable softplus
    float sp0 = fmaxf(xn0, 0.f) + log1pf(__expf(-fabsf(xn0)));
    float sp1 = fmaxf(xn1, 0.f) + log1pf(__expf(-fabsf(xn1)));

    // double normalization (warp-local)
    float v = sp0 + sp1;
    #pragma unroll
    for (int o = 16; o; o >>= 1) v += __shfl_xor_sync(0xffffffffu, v, o);
    float s1 = v + EPSF;
    float q0 = fmaxf(sp0/s1, EPSF), q1 = fmaxf(sp1/s1, EPSF);
    v = q0 + q1;
    #pragma unroll
    for (int o = 16; o; o >>= 1) v += __shfl_xor_sync(0xffffffffu, v, o);
    float s2 = v + EPSF;
    float p0 = q0/s2, p1 = q1/s2;

    float u0 = sqrtf(p0), u1 = sqrtf(p1);
    sfeat[c][wid]       = u0;
    sfeat[c+32][wid]    = u1;
    sfeat[64+c][wid]    = C2F/u0;
    sfeat[96+c][wid]    = C2F/u1;
    __syncthreads();

    // packed transposed store: dim-pair major, 16 tokens contiguous
    #pragma unroll
    for (int i = tid; i < (FDIM/2)*16; i += 512) {
        int dp = i >> 4, t = i & 15;
        g_featP[dp*NTOK + tok0 + t] = make_float2(sfeat[2*dp][t], sfeat[2*dp+1][t]);
    }
}

// ---------------------------------------------------------------------------
// attention: 4 rows/block, grid 256 (2 blocks/SM), 512 threads (16 warps).
// Phase1: lane owns j = w*32+c; 128-dot via f32x2 row-pair accumulators,
// dim-pair packed j loads, prefetched. Phase3: dim-pair packed x loads.
__global__ void __launch_bounds__(512, 2)
k_attn(int cursel, int l, int snap, int fin,
       const float* __restrict__ seq, const float* __restrict__ resg,
       float* __restrict__ out) {
    const float* xin = cursel ? g_bufB : g_bufA;
    float*       xout = cursel ? g_bufA : g_bufB;

    int blk = blockIdx.x;
    int b = blk >> 7;                    // 128 blocks per batch
    int rowBase = (blk & 127) << 2;      // *4
    int tid = threadIdx.x, w = tid >> 5, c = tid & 31;

    __shared__ __align__(16) u64 rf2s[FDIM][2];     // [dim][rowpair] packed rows
    __shared__ __align__(16) u64 LePr[2][TT];       // e row-pairs per j
    __shared__ float wSum[16][4];
    __shared__ __align__(16) u64 wFA[16][2][32];    // partials: dim 2c
    __shared__ __align__(16) u64 wFB[16][2][32];    // partials: dim 2c+1

    float nInvT = -1.f / fmaxf(g_temps[l], 1e-6f);

    // stage row features: 256 threads, thread = (dim dd, rowpair rp)
    if (tid < 256) {
        int dd = tid >> 1, rp = tid & 1;
        const float* gfp = (const float*)g_featP;
        int base = (dd >> 1)*(2*NTOK) + (dd & 1);
        int t0 = b*TT + rowBase + 2*rp;
        float f0 = gfp[base + 2*t0];
        float f1 = gfp[base + 2*(t0+1)];
        rf2s[dd][rp] = pack2(f0, f1);
    }
    __syncthreads();

    // phase 1: 128-dot for this lane's j, 4 rows via 2 packed accumulators
    int jl = w*32 + c;
    const float2* fp = g_featP + b*TT + jl;
    u64 acc0 = 0ull, acc1 = 0ull;
    float2 jv[4], jvn[4];
    #pragma unroll
    for (int q = 0; q < 4; ++q) jv[q] = fp[q*NTOK];
    #pragma unroll 1
    for (int dp0 = 0; dp0 < FDIM/2; dp0 += 4) {
        if (dp0 + 4 < FDIM/2) {
            #pragma unroll
            for (int q = 0; q < 4; ++q) jvn[q] = fp[(dp0+4+q)*NTOK];
        }
        #pragma unroll
        for (int q = 0; q < 4; ++q) {
            int dp = dp0 + q;
            const ulonglong2 rA = *(const ulonglong2*)&rf2s[2*dp][0];
            const ulonglong2 rB = *(const ulonglong2*)&rf2s[2*dp+1][0];
            u64 jx = bcast2(jv[q].x);
            u64 jy = bcast2(jv[q].y);
            fma2(acc0, rA.x, jx);
            fma2(acc1, rA.y, jx);
            fma2(acc0, rB.x, jy);
            fma2(acc1, rB.y, jy);
        }
        #pragma unroll
        for (int q = 0; q < 4; ++q) jv[q] = jvn[q];
    }

    // e = exp(2*acos(clip)*nInvT) (no-max softmax: logits in [-12.6, 0])
    float i0, i1, i2, i3;
    unpack2(acc0, i0, i1);
    unpack2(acc1, i2, i3);
    i0 = fminf(fmaxf(i0, -1.f + 1e-6f), 1.f - 1e-6f);
    i1 = fminf(fmaxf(i1, -1.f + 1e-6f), 1.f - 1e-6f);
    i2 = fminf(fmaxf(i2, -1.f + 1e-6f), 1.f - 1e-6f);
    i3 = fminf(fmaxf(i3, -1.f + 1e-6f), 1.f - 1e-6f);
    float e0 = __expf(2.f*acos_fast(i0)*nInvT);
    float e1 = __expf(2.f*acos_fast(i1)*nInvT);
    float e2 = __expf(2.f*acos_fast(i2)*nInvT);
    float e3 = __expf(2.f*acos_fast(i3)*nInvT);
    LePr[0][jl] = pack2(e0, e1);
    LePr[1][jl] = pack2(e2, e3);
    float es[4] = {e0, e1, e2, e3};
    #pragma unroll
    for (int r = 0; r < 4; ++r) {
        float sv = es[r];
        #pragma unroll
        for (int o = 16; o; o >>= 1) sv += __shfl_xor_sync(0xffffffffu, sv, o);
        if (c == 0) wSum[w][r] = sv;
    }
    __syncthreads();

    // phase 3: value accumulation, 16 warps x 32 j, dim-pair packed x
    {
        u64 fA0 = 0ull, fA1 = 0ull, fB0 = 0ull, fB1 = 0ull;
        const float2* xb2 = (const float2*)(xin + b*TT*DD);
        int j0 = w*32;
        float2 xv = xb2[j0*32 + c];
        #pragma unroll 4
        for (int jj = 0; jj < 32; ++jj) {
            int j = j0 + jj;
            float2 nx = make_float2(0.f, 0.f);
            if (jj < 31) nx = xb2[(j+1)*32 + c];
            u64 ep0 = LePr[0][j];
            u64 ep1 = LePr[1][j];
            u64 xA = bcast2(xv.x), xB = bcast2(xv.y);
            fma2(fA0, ep0, xA);
            fma2(fA1, ep1, xA);
            fma2(fB0, ep0, xB);
            fma2(fB1, ep1, xB);
            xv = nx;
        }
        wFA[w][0][c] = fA0; wFA[w][1][c] = fA1;
        wFB[w][0][c] = fB0; wFB[w][1][c] = fB1;
    }
    __syncthreads();

    // merge: thread = (row r, dim d), 256 threads
    if (tid < 256) {
        int r = tid >> 6, d = tid & 63;
        int q = r >> 1, sel = r & 1;
        int cc = d >> 1, ab = d & 1;
        float F = 0.f, S = 0.f;
        #pragma unroll
        for (int ww = 0; ww < 16; ++ww) {
            u64 fp2 = ab ? wFB[ww][q][cc] : wFA[ww][q][cc];
            float lo, hi;
            unpack2(fp2, lo, hi);
            F += sel ? hi : lo;
            S += wSum[ww][r];
        }
        int tok = b*TT + rowBase + r;
        float rs = g_res[l];
        float xv = xin[tok*DD + d];
        float o = xv + rs*(F/S - xv);
        xout[tok*DD + d] = o;
        if (snap) g_prev[l][tok*DD + d] = o;
        if (fin)  out[tok*DD + d] = o + 0.01f*resg[0]*(o - seq[tok*DD + d]);
    }
}

// ---------------------------------------------------------------------------
__global__ void __launch_bounds__(512) k_pool(int cursel,
                       const float* __restrict__ Wc1, const float* __restrict__ bc1,
                       const float* __restrict__ Wc2, const float* __restrict__ bc2,
                       const float* __restrict__ Wu,  const float* __restrict__ bu,
                       const float* __restrict__ W_temp, const float* __restrict__ b_temp) {
    const float* x = cursel ? g_bufB : g_bufA;
    int tid = threadIdx.x;
    __shared__ float part[4][BB*DD];
    __shared__ float pooled[BB][DD];
    __shared__ float h1[BB][HH];
    __shared__ float hb[BB][DD];
    __shared__ float agg[DD], comb[2*DD], nb[DD];

    {
        int it = tid & 127, ch = tid >> 7;
        int b = it >> 6, d = it & 63;
        float s = 0.f;
        const float* xb = x + b*TT*DD + d;
        #pragma unroll 8
        for (int t = ch*128; t < ch*128 + 128; ++t) s += xb[t*DD];
        part[ch][it] = s;
    }
    __syncthreads();
    if (tid < 128) {
        pooled[tid>>6][tid&63] =
            (part[0][tid] + part[1][tid] + part[2][tid] + part[3][tid]) * (1.f/TT);
    }
    __syncthreads();
    if (tid < BB*HH) {
        int bb = tid / HH, h = tid - bb*HH;
        float a = bc1[h];
        #pragma unroll 8
        for (int k = 0; k < DD; ++k) a = fmaf(pooled[bb][k], Wc1[h*DD + k], a);
        h1[bb][h] = tanhf(a);
    }
    __syncthreads();
    if (tid < 128) {
        int b = tid >> 6, d = tid & 63;
        float a = bc2[d];
        #pragma unroll 8
        for (int k = 0; k < HH; ++k) a = fmaf(h1[b][k], Wc2[d*HH + k], a);
        hb[b][d] = tanhf(a);
    }
    __syncthreads();
    if (tid < DD) {
        float a = 0.5f*(hb[0][tid] + hb[1][tid]);
        agg[tid]      = a;
        comb[tid]     = g_basin[tid];
        comb[DD+tid]  = a;
    }
    __syncthreads();
    if (tid < DD) {
        float a = bu[tid];
        #pragma unroll 8
        for (int k = 0; k < 2*DD; ++k) a = fmaf(Wu[tid*2*DD + k], comb[k], a);
        float g = 1.f/(1.f + expf(-a));
        nb[tid] = g_basin[tid]*(1.f - g) + agg[tid]*g;
        g_basin[tid] = nb[tid];
    }
    __syncthreads();
    if (tid < LAYERS) {
        float acc = b_temp[tid];
        #pragma unroll 8
        for (int k = 0; k < DD; ++k) acc = fmaf(W_temp[tid*DD + k], nb[k], acc);
        g_temps[tid] = 1.f/(1.f + expf(-acc)) + 0.5f;
    }
}

// ---------------------------------------------------------------------------
extern "C" void kernel_launch(void* const* d_in, const int* in_sizes, int n_in,
                              void* d_out, int out_size) {
    const float* basin_seq    = (const float*)d_in[0];
    const float* basin_coords = (const float*)d_in[1];
    const float* W_temp       = (const float*)d_in[2];
    const float* b_temp       = (const float*)d_in[3];
    const float* res_scale    = (const float*)d_in[4];
    const float* W_fb         = (const float*)d_in[5];
    const float* b_fb         = (const float*)d_in[6];
    const float* Wc1          = (const float*)d_in[7];
    const float* bc1          = (const float*)d_in[8];
    const float* Wc2          = (const float*)d_in[9];
    const float* bc2          = (const float*)d_in[10];
    const float* Wu           = (const float*)d_in[11];
    const float* bu           = (const float*)d_in[12];
    const float* res_g        = (const float*)d_in[13];

    k_copy<<<NTOK*DD/512, 512>>>(basin_seq);
    k_init<<<1, 64>>>(basin_coords, W_temp, b_temp, res_scale);

    int cursel = 0;
    for (int p = 0; p < 2; ++p) {
        for (int l = 0; l < LAYERS; ++l) {
            int last = (p == 1 && l == LAYERS-1);
            k_feat<<<NTOK/16, 512>>>(cursel, l, p > 0 ? 1 : 0, W_fb, b_fb);
            k_attn<<<NTOK/4, 512>>>(cursel, l, p == 0 ? 1 : 0, last,
                                    basin_seq, res_g, (float*)d_out);
            cursel ^= 1;
        }
        if (p == 0) {
            k_pool<<<1, 512>>>(cursel, Wc1, bc1, Wc2, bc2, Wu, bu, W_temp, b_temp);
        }
    }
}

// round 7
// speedup vs baseline: 3.0209x; 1.1139x over previous
#include <cuda_runtime.h>
#include <math.h>

#define BB 2
#define TT 512
#define DD 64
#define LAYERS 4
#define HH 32
#define NTOK (BB*TT)
#define FDIM 128            // u (64) + v (64)
#define EPSF 1e-8f
#define C2F 7.0710678e-5f   // sqrt(EPS/2)

__device__ float g_bufA[NTOK*DD];
__device__ float g_bufB[NTOK*DD];
__device__ float g_prev[LAYERS][NTOK*DD];
__device__ float2 g_featP[(FDIM/2)*NTOK];   // [dimpair][token] packed
__device__ float g_basin[DD];
__device__ float g_temps[LAYERS];
__device__ float g_res[LAYERS];

typedef unsigned long long u64;
typedef unsigned int u32;

__device__ __forceinline__ u64 pack2(float x, float y) {
    u64 r;
    asm("mov.b64 %0, {%1, %2};" : "=l"(r) : "r"(__float_as_uint(x)), "r"(__float_as_uint(y)));
    return r;
}
__device__ __forceinline__ u64 bcast2(float x) { return pack2(x, x); }
__device__ __forceinline__ void fma2(u64& d, u64 a, u64 b) {
    asm("fma.rn.f32x2 %0, %1, %2, %0;" : "+l"(d) : "l"(a), "l"(b));
}
__device__ __forceinline__ void unpack2(u64 v, float& lo, float& hi) {
    u32 a, b;
    asm("mov.b64 {%0, %1}, %2;" : "=r"(a), "=r"(b) : "l"(v));
    lo = __uint_as_float(a); hi = __uint_as_float(b);
}

// acos for x in [-1,1], |err| ~2e-8 (A&S 4.4.45)
__device__ __forceinline__ float acos_fast(float x) {
    float ax = fabsf(x);
    float r = sqrtf(1.0f - ax);
    float p = fmaf(ax, -0.0012624911f, 0.0066700901f);
    p = fmaf(ax, p, -0.0170881256f);
    p = fmaf(ax, p, 0.0308918810f);
    p = fmaf(ax, p, -0.0501743046f);
    p = fmaf(ax, p, 0.0889789874f);
    p = fmaf(ax, p, -0.2145988016f);
    p = fmaf(ax, p, 1.5707963050f);
    float res = r * p;
    return (x < 0.f) ? (3.14159265358979f - res) : res;
}

// ---------------------------------------------------------------------------
__global__ void __launch_bounds__(512) k_copy(const float* __restrict__ src) {
    int i = blockIdx.x*512 + threadIdx.x;
    g_bufA[i] = src[i];
}

// ---------------------------------------------------------------------------
__global__ void k_init(const float* __restrict__ basin_coords,
                       const float* __restrict__ W_temp,
                       const float* __restrict__ b_temp,
                       const float* __restrict__ res_scale) {
    int t = threadIdx.x;           // 64 threads
    __shared__ float sb[DD];
    sb[t] = basin_coords[t];
    g_basin[t] = sb[t];
    __syncthreads();
    if (t < LAYERS) {
        g_res[t] = res_scale[t];
        float acc = b_temp[t];
        #pragma unroll 8
        for (int d = 0; d < DD; ++d) acc = fmaf(W_temp[t*DD + d], sb[d], acc);
        g_temps[t] = 1.f/(1.f + expf(-acc)) + 0.5f;
    }
}

// ---------------------------------------------------------------------------
// feat0: ungated features for pass0/layer0. 16 tokens/block, warp = token.
__global__ void __launch_bounds__(512) k_feat0() {
    const float* x = g_bufA;
    int tid = threadIdx.x;
    int wid = tid >> 5, c = tid & 31;
    int tok0 = blockIdx.x * 16;
    int tok = tok0 + wid;

    __shared__ float sfeat[FDIM][17];

    float xn0 = x[tok*64 + c];
    float xn1 = x[tok*64 + c + 32];

    float sp0 = fmaxf(xn0, 0.f) + log1pf(__expf(-fabsf(xn0)));
    float sp1 = fmaxf(xn1, 0.f) + log1pf(__expf(-fabsf(xn1)));

    float v = sp0 + sp1;
    #pragma unroll
    for (int o = 16; o; o >>= 1) v += __shfl_xor_sync(0xffffffffu, v, o);
    float s1 = v + EPSF;
    float q0 = fmaxf(sp0/s1, EPSF), q1 = fmaxf(sp1/s1, EPSF);
    v = q0 + q1;
    #pragma unroll
    for (int o = 16; o; o >>= 1) v += __shfl_xor_sync(0xffffffffu, v, o);
    float s2 = v + EPSF;
    float p0 = q0/s2, p1 = q1/s2;

    float u0 = sqrtf(p0), u1 = sqrtf(p1);
    sfeat[c][wid]       = u0;
    sfeat[c+32][wid]    = u1;
    sfeat[64+c][wid]    = C2F/u0;
    sfeat[96+c][wid]    = C2F/u1;
    __syncthreads();

    #pragma unroll
    for (int i = tid; i < (FDIM/2)*16; i += 512) {
        int dp = i >> 4, t = i & 15;
        g_featP[dp*NTOK + tok0 + t] = make_float2(sfeat[2*dp][t], sfeat[2*dp+1][t]);
    }
}

// ---------------------------------------------------------------------------
// attention + fused next-layer feature build.
// 4 rows/block, grid 256, 512 threads, 2 blocks/SM.
__global__ void __launch_bounds__(512, 2)
k_attn(int cursel, int l, int snap, int fin, int doFeat, int nextGated, int nextL,
       const float* __restrict__ W_fb, const float* __restrict__ b_fb,
       const float* __restrict__ seq, const float* __restrict__ resg,
       float* __restrict__ out) {
    const float* xin = cursel ? g_bufB : g_bufA;
    float*       xout = cursel ? g_bufA : g_bufB;

    int blk = blockIdx.x;
    int b = blk >> 7;
    int rowBase = (blk & 127) << 2;
    int tid = threadIdx.x, w = tid >> 5, c = tid & 31;

    // blob: LePr (8K) | wFA (8K) | wFB (8K). sWh (GEMV stage, 19456B) aliases
    // LePr+wFA+start of wFB, all dead by the time the epilogue GEMV runs.
    __shared__ __align__(16) char smemBlob[24576];
    u64 (*LePr)[2]     = (u64(*)[2])(smemBlob);            // [TT][rowpair]
    u64 (*wFA)[2][32]  = (u64(*)[2][32])(smemBlob + 8192);
    u64 (*wFB)[2][32]  = (u64(*)[2][32])(smemBlob + 16384);
    float* sWh         = (float*)smemBlob;                 // [64][76]

    __shared__ __align__(16) u64 rf2s[FDIM][2];   // [dim][rowpair] packed rows
    __shared__ float so[4][64], sprev[4][64];
    __shared__ float su[64][5], sv[64][5];
    __shared__ float wSum[16][4];
    __shared__ float sred[4][4];

    float nInvT = -1.f / fmaxf(g_temps[l], 1e-6f);

    // stage row features: thread = (dim dd, rowpair rp)
    if (tid < 256) {
        int dd = tid >> 1, rp = tid & 1;
        const float* gfp = (const float*)g_featP;
        int base = (dd >> 1)*(2*NTOK) + (dd & 1);
        int t0 = b*TT + rowBase + 2*rp;
        float f0 = gfp[base + 2*t0];
        float f1 = gfp[base + 2*(t0+1)];
        rf2s[dd][rp] = pack2(f0, f1);
    }
    __syncthreads();

    // phase 1: 128-dot for this lane's j, 4 rows via 2 packed accumulators
    int jl = w*32 + c;
    const float2* fp = g_featP + b*TT + jl;
    u64 acc0 = 0ull, acc1 = 0ull;
    float2 jv[4], jvn[4];
    #pragma unroll
    for (int q = 0; q < 4; ++q) { jv[q] = fp[q*NTOK]; jvn[q] = make_float2(0.f, 0.f); }
    #pragma unroll 1
    for (int dp0 = 0; dp0 < FDIM/2; dp0 += 4) {
        if (dp0 + 4 < FDIM/2) {
            #pragma unroll
            for (int q = 0; q < 4; ++q) jvn[q] = fp[(dp0+4+q)*NTOK];
        }
        #pragma unroll
        for (int q = 0; q < 4; ++q) {
            int dp = dp0 + q;
            const ulonglong2 rA = *(const ulonglong2*)&rf2s[2*dp][0];
            const ulonglong2 rB = *(const ulonglong2*)&rf2s[2*dp+1][0];
            u64 jx = bcast2(jv[q].x);
            u64 jy = bcast2(jv[q].y);
            fma2(acc0, rA.x, jx);
            fma2(acc1, rA.y, jx);
            fma2(acc0, rB.x, jy);
            fma2(acc1, rB.y, jy);
        }
        #pragma unroll
        for (int q = 0; q < 4; ++q) jv[q] = jvn[q];
    }

    // e = exp(2*acos(clip)*nInvT) (no-max softmax: logits in [-12.6, 0])
    float i0, i1, i2, i3;
    unpack2(acc0, i0, i1);
    unpack2(acc1, i2, i3);
    i0 = fminf(fmaxf(i0, -1.f + 1e-6f), 1.f - 1e-6f);
    i1 = fminf(fmaxf(i1, -1.f + 1e-6f), 1.f - 1e-6f);
    i2 = fminf(fmaxf(i2, -1.f + 1e-6f), 1.f - 1e-6f);
    i3 = fminf(fmaxf(i3, -1.f + 1e-6f), 1.f - 1e-6f);
    float e0 = __expf(2.f*acos_fast(i0)*nInvT);
    float e1 = __expf(2.f*acos_fast(i1)*nInvT);
    float e2 = __expf(2.f*acos_fast(i2)*nInvT);
    float e3 = __expf(2.f*acos_fast(i3)*nInvT);
    {
        ulonglong2 ev;
        ev.x = pack2(e0, e1);
        ev.y = pack2(e2, e3);
        *(ulonglong2*)&LePr[jl][0] = ev;
    }
    float es[4] = {e0, e1, e2, e3};
    #pragma unroll
    for (int r = 0; r < 4; ++r) {
        float sv2 = es[r];
        #pragma unroll
        for (int o = 16; o; o >>= 1) sv2 += __shfl_xor_sync(0xffffffffu, sv2, o);
        if (c == 0) wSum[w][r] = sv2;
    }
    __syncthreads();

    // phase 3: value accumulation, 16 warps x 32 j, dim-pair packed x
    {
        u64 fA0 = 0ull, fA1 = 0ull, fB0 = 0ull, fB1 = 0ull;
        const float2* xb2 = (const float2*)(xin + b*TT*DD);
        int j0 = w*32;
        float2 xv = xb2[j0*32 + c];
        #pragma unroll 4
        for (int jj = 0; jj < 32; ++jj) {
            int j = j0 + jj;
            float2 nx = make_float2(0.f, 0.f);
            if (jj < 31) nx = xb2[(j+1)*32 + c];
            ulonglong2 ep = *(const ulonglong2*)&LePr[j][0];
            u64 xA = bcast2(xv.x), xB = bcast2(xv.y);
            fma2(fA0, ep.x, xA);
            fma2(fA1, ep.y, xA);
            fma2(fB0, ep.x, xB);
            fma2(fB1, ep.y, xB);
            xv = nx;
        }
        wFA[w][0][c] = fA0; wFA[w][1][c] = fA1;
        wFB[w][0][c] = fB0; wFB[w][1][c] = fB1;
    }
    __syncthreads();

    // merge: thread = (row r, dim d), 256 threads
    int r = tid >> 6, d = tid & 63;
    int rr = r & 3;
    if (tid < 256) {
        int q = r >> 1, sel = r & 1;
        int cc = d >> 1, ab = d & 1;
        float F = 0.f, S = 0.f;
        #pragma unroll
        for (int ww = 0; ww < 16; ++ww) {
            u64 fp2 = ab ? wFB[ww][q][cc] : wFA[ww][q][cc];
            float lo, hi;
            unpack2(fp2, lo, hi);
            F += sel ? hi : lo;
            S += wSum[ww][r];
        }
        int tok = b*TT + rowBase + r;
        float rs = g_res[l];
        float xv = xin[tok*DD + d];
        float o = xv + rs*(F/S - xv);
        so[r][d] = o;
        if (snap) g_prev[l][tok*DD + d] = o;
        if (!(doFeat && nextGated)) xout[tok*DD + d] = o;
        if (fin)  out[tok*DD + d] = o + 0.01f*resg[0]*(o - seq[tok*DD + d]);
        if (doFeat && nextGated) sprev[r][d] = g_prev[nextL][tok*DD + d];
    }
    if (!doFeat) return;
    __syncthreads();

    // ------- fused next-layer feature build -------
    float xfeat = 0.f;
    if (nextGated) {
        // stage W x-half into dead smem (64 rows x 64 cols, pad 76)
        const float* Wg = W_fb + nextL*DD*2*DD;
        #pragma unroll
        for (int i = tid; i < 64*64; i += 512)
            sWh[(i>>6)*76 + (i&63)] = Wg[(i>>6)*128 + (i&63)];
        __syncthreads();
        float acc = 0.f;
        if (tid < 256) {
            acc = b_fb[nextL*DD + d];
            const float4* Wr = (const float4*)&sWh[d*76];
            const float4* xr4 = (const float4*)&so[rr][0];
            #pragma unroll
            for (int q2 = 0; q2 < 16; ++q2) {
                float4 wv = Wr[q2], vv = xr4[q2];
                acc += wv.x*vv.x + wv.y*vv.y + wv.z*vv.z + wv.w*vv.w;
            }
        }
        __syncthreads();
        // stage W prev-half
        #pragma unroll
        for (int i = tid; i < 64*64; i += 512)
            sWh[(i>>6)*76 + (i&63)] = Wg[(i>>6)*128 + 64 + (i&63)];
        __syncthreads();
        if (tid < 256) {
            const float4* Wr = (const float4*)&sWh[d*76];
            const float4* pr4 = (const float4*)&sprev[rr][0];
            #pragma unroll
            for (int q2 = 0; q2 < 16; ++q2) {
                float4 wv = Wr[q2], vv = pr4[q2];
                acc += wv.x*vv.x + wv.y*vv.y + wv.z*vv.z + wv.w*vv.w;
            }
            float g = 1.f/(1.f + __expf(-acc));
            xfeat = so[rr][d]*g + sprev[rr][d]*(1.f - g);
            int tok = b*TT + rowBase + rr;
            xout[tok*DD + d] = xfeat;
        }
    } else {
        xfeat = so[rr][d];
    }

    // simplex projection per token (dims of token rr live in 2 warps)
    float sp = fmaxf(xfeat, 0.f) + log1pf(__expf(-fabsf(xfeat)));
    int half = (d >> 5) & 1;
    float v1 = sp;
    #pragma unroll
    for (int o = 16; o; o >>= 1) v1 += __shfl_xor_sync(0xffffffffu, v1, o);
    if (tid < 256 && (tid & 31) == 0) sred[r][half] = v1;
    __syncthreads();
    float s1 = sred[rr][0] + sred[rr][1] + EPSF;
    float sfrac = fmaxf(sp/s1, EPSF);
    float v2 = sfrac;
    #pragma unroll
    for (int o = 16; o; o >>= 1) v2 += __shfl_xor_sync(0xffffffffu, v2, o);
    if (tid < 256 && (tid & 31) == 0) sred[r][2 + half] = v2;
    __syncthreads();
    float s2 = sred[rr][2] + sred[rr][3] + EPSF;
    float pfin = sfrac/s2;

    if (tid < 256) {
        float u = sqrtf(pfin);
        su[d][r] = u;
        sv[d][r] = C2F/u;
    }
    __syncthreads();

    // write packed features for the block's 4 tokens
    if (tid < 256) {
        int dp = tid >> 2, tk = tid & 3;
        int d0 = 2*dp, d1 = 2*dp + 1;
        float f0 = (d0 < 64) ? su[d0][tk] : sv[d0-64][tk];
        float f1 = (d1 < 64) ? su[d1][tk] : sv[d1-64][tk];
        g_featP[dp*NTOK + b*TT + rowBase + tk] = make_float2(f0, f1);
    }
}

// ---------------------------------------------------------------------------
// pool reads the snapped pass-0 layer-3 state (pre-gate).
__global__ void __launch_bounds__(512) k_pool(
                       const float* __restrict__ Wc1, const float* __restrict__ bc1,
                       const float* __restrict__ Wc2, const float* __restrict__ bc2,
                       const float* __restrict__ Wu,  const float* __restrict__ bu,
                       const float* __restrict__ W_temp, const float* __restrict__ b_temp) {
    const float* x = &g_prev[LAYERS-1][0];
    int tid = threadIdx.x;
    __shared__ float part[4][BB*DD];
    __shared__ float pooled[BB][DD];
    __shared__ float h1[BB][HH];
    __shared__ float hb[BB][DD];
    __shared__ float agg[DD], comb[2*DD], nb[DD];

    {
        int it = tid & 127, ch = tid >> 7;
        int b = it >> 6, d = it & 63;
        float s = 0.f;
        const float* xb = x + b*TT*DD + d;
        #pragma unroll 8
        for (int t = ch*128; t < ch*128 + 128; ++t) s += xb[t*DD];
        part[ch][it] = s;
    }
    __syncthreads();
    if (tid < 128) {
        pooled[tid>>6][tid&63] =
            (part[0][tid] + part[1][tid] + part[2][tid] + part[3][tid]) * (1.f/TT);
    }
    __syncthreads();
    if (tid < BB*HH) {
        int bb = tid / HH, h = tid - bb*HH;
        float a = bc1[h];
        #pragma unroll 8
        for (int k = 0; k < DD; ++k) a = fmaf(pooled[bb][k], Wc1[h*DD + k], a);
        h1[bb][h] = tanhf(a);
    }
    __syncthreads();
    if (tid < 128) {
        int b = tid >> 6, d = tid & 63;
        float a = bc2[d];
        #pragma unroll 8
        for (int k = 0; k < HH; ++k) a = fmaf(h1[b][k], Wc2[d*HH + k], a);
        hb[b][d] = tanhf(a);
    }
    __syncthreads();
    if (tid < DD) {
        float a = 0.5f*(hb[0][tid] + hb[1][tid]);
        agg[tid]      = a;
        comb[tid]     = g_basin[tid];
        comb[DD+tid]  = a;
    }
    __syncthreads();
    if (tid < DD) {
        float a = bu[tid];
        #pragma unroll 8
        for (int k = 0; k < 2*DD; ++k) a = fmaf(Wu[tid*2*DD + k], comb[k], a);
        float g = 1.f/(1.f + expf(-a));
        nb[tid] = g_basin[tid]*(1.f - g) + agg[tid]*g;
        g_basin[tid] = nb[tid];
    }
    __syncthreads();
    if (tid < LAYERS) {
        float acc = b_temp[tid];
        #pragma unroll 8
        for (int k = 0; k < DD; ++k) acc = fmaf(W_temp[tid*DD + k], nb[k], acc);
        g_temps[tid] = 1.f/(1.f + expf(-acc)) + 0.5f;
    }
}

// ---------------------------------------------------------------------------
extern "C" void kernel_launch(void* const* d_in, const int* in_sizes, int n_in,
                              void* d_out, int out_size) {
    const float* basin_seq    = (const float*)d_in[0];
    const float* basin_coords = (const float*)d_in[1];
    const float* W_temp       = (const float*)d_in[2];
    const float* b_temp       = (const float*)d_in[3];
    const float* res_scale    = (const float*)d_in[4];
    const float* W_fb         = (const float*)d_in[5];
    const float* b_fb         = (const float*)d_in[6];
    const float* Wc1          = (const float*)d_in[7];
    const float* bc1          = (const float*)d_in[8];
    const float* Wc2          = (const float*)d_in[9];
    const float* bc2          = (const float*)d_in[10];
    const float* Wu           = (const float*)d_in[11];
    const float* bu           = (const float*)d_in[12];
    const float* res_g        = (const float*)d_in[13];

    k_copy<<<NTOK*DD/512, 512>>>(basin_seq);
    k_init<<<1, 64>>>(basin_coords, W_temp, b_temp, res_scale);
    k_feat0<<<NTOK/16, 512>>>();

    int cursel = 0;
    for (int p = 0; p < 2; ++p) {
        for (int l = 0; l < LAYERS; ++l) {
            int last = (p == 1 && l == LAYERS-1);
            int doFeat = !last;
            int nextGated = (p == 1) || (l == LAYERS-1);
            int nextL = (l + 1) & 3;
            k_attn<<<NTOK/4, 512>>>(cursel, l, p == 0 ? 1 : 0, last, doFeat,
                                    nextGated, nextL, W_fb, b_fb,
                                    basin_seq, res_g, (float*)d_out);
            cursel ^= 1;
            if (p == 0 && l == LAYERS-1) {
                k_pool<<<1, 512>>>(Wc1, bc1, Wc2, bc2, Wu, bu, W_temp, b_temp);
            }
        }
    }
}